// round 6
// baseline (speedup 1.0000x reference)
#include <cuda_runtime.h>
#include <math.h>
#include <stdint.h>

// Problem constants
#define Bc  4
#define Sc  2048
#define Dc  1024
#define Hc  16
#define HDc 64
#define Fc  4096
#define Nc  2048

// ---------------- scratch (__device__ globals; no cudaMalloc allowed) ----------------
__device__ float g_sel[Nc * Dc];
__device__ float g_h[Nc * Dc];
__device__ float g_cg[Nc * HDc];
__device__ float g_sg[Nc * HDc];
__device__ float g_q[Nc * Dc];
__device__ float g_k[Nc * Dc];
__device__ float g_v[Nc * Dc];
__device__ float g_ctx[Nc * Dc];
__device__ float g_h2[Nc * Dc];
__device__ float g_m[Nc * Dc];
__device__ float g_gate[Nc * Fc];
__device__ float g_up[Nc * Fc];

// ---------------- helpers ----------------
__device__ __forceinline__ uint32_t sptr(const void* p) {
    return (uint32_t)__cvta_generic_to_shared(p);
}
__device__ __forceinline__ void cp16(uint32_t s, const void* g) {
    asm volatile("cp.async.cg.shared.global [%0], [%1], 16;\n" :: "r"(s), "l"(g));
}
__device__ __forceinline__ void cp_commit() { asm volatile("cp.async.commit_group;\n"); }
template<int W> __device__ __forceinline__ void cp_wait() {
    asm volatile("cp.async.wait_group %0;\n" :: "n"(W));
}

// raw fp32 bits fed to tf32 mma: HW truncates mantissa to tf32 precision.
__device__ __forceinline__ void mma_tf32(float* c, const uint32_t* a, const uint32_t* b) {
    asm volatile(
        "mma.sync.aligned.m16n8k8.row.col.f32.tf32.tf32.f32 "
        "{%0,%1,%2,%3}, {%4,%5,%6,%7}, {%8,%9}, {%0,%1,%2,%3};"
        : "+f"(c[0]), "+f"(c[1]), "+f"(c[2]), "+f"(c[3])
        : "r"(a[0]), "r"(a[1]), "r"(a[2]), "r"(a[3]), "r"(b[0]), "r"(b[1]));
}

// ---------------- plain copy: hidden -> out ----------------
__global__ __launch_bounds__(256) void copy_kernel(
    const float4* __restrict__ src, float4* __restrict__ dst)
{
    int i = blockIdx.x * 256 + threadIdx.x;
    dst[i] = src[i];
}

// ---------------- gather + RMSNorm(ln1), plus cos/sin gather ----------------
__global__ __launch_bounds__(256) void gather_norm_kernel(
    const float* __restrict__ hidden, const int* __restrict__ bi,
    const int* __restrict__ ti, const float* __restrict__ cosp,
    const float* __restrict__ sinp, const float* __restrict__ ln1)
{
    int n = blockIdx.x;
    int b = bi[n], t = ti[n];
    const float* row = hidden + ((size_t)b * Sc + t) * Dc;
    float vals[4];
    float local = 0.f;
#pragma unroll
    for (int i = 0; i < 4; i++) {
        float x = row[threadIdx.x + 256 * i];
        vals[i] = x;
        local += x * x;
    }
    __shared__ float red[256];
    red[threadIdx.x] = local;
    __syncthreads();
    for (int s = 128; s > 0; s >>= 1) {
        if (threadIdx.x < s) red[threadIdx.x] += red[threadIdx.x + s];
        __syncthreads();
    }
    float inv = rsqrtf(red[0] / (float)Dc + 1e-6f);
#pragma unroll
    for (int i = 0; i < 4; i++) {
        int d = threadIdx.x + 256 * i;
        g_sel[(size_t)n * Dc + d] = vals[i];
        g_h[(size_t)n * Dc + d] = vals[i] * inv * ln1[d];
    }
    if (threadIdx.x < HDc) {
        size_t src = ((size_t)b * Sc + t) * HDc + threadIdx.x;
        g_cg[n * HDc + threadIdx.x] = cosp[src];
        g_sg[n * HDc + threadIdx.x] = sinp[src];
    }
}

// ---------------- RMSNorm(ln2): g_h2 -> g_m ----------------
__global__ __launch_bounds__(256) void rmsnorm2_kernel(const float* __restrict__ ln2)
{
    int n = blockIdx.x;
    const float* row = g_h2 + (size_t)n * Dc;
    float vals[4];
    float local = 0.f;
#pragma unroll
    for (int i = 0; i < 4; i++) {
        float x = row[threadIdx.x + 256 * i];
        vals[i] = x;
        local += x * x;
    }
    __shared__ float red[256];
    red[threadIdx.x] = local;
    __syncthreads();
    for (int s = 128; s > 0; s >>= 1) {
        if (threadIdx.x < s) red[threadIdx.x] += red[threadIdx.x + s];
        __syncthreads();
    }
    float inv = rsqrtf(red[0] / (float)Dc + 1e-6f);
#pragma unroll
    for (int i = 0; i < 4; i++) {
        int d = threadIdx.x + 256 * i;
        g_m[(size_t)n * Dc + d] = vals[i] * inv * ln2[d];
    }
}

// ---------------- pipelined tf32 GEMM: C_w = A @ B_w (+bias_w) (+res) ----------------
// Block tile 128 x BN (BN = NI*32), BK=32, 256 threads, 8 warps (2x4),
// warp tile 64 x (NI*8). 2-stage cp.async, ONE __syncthreads per K-tile.
// Optional fused gated-scatter epilogue (outp != nullptr):
//   out[bi[r], ti[r], col] = sel + gs[r] * ((acc + res) - sel)
template<int NI>
__global__ __launch_bounds__(256) void tgemm_kernel(
    const float* __restrict__ A, int K,
    const float* __restrict__ B0, const float* __restrict__ B1, const float* __restrict__ B2,
    const float* __restrict__ bias0, const float* __restrict__ bias1, const float* __restrict__ bias2,
    const float* __restrict__ res,
    float* __restrict__ C0, float* __restrict__ C1, float* __restrict__ C2,
    int ldo, int blocksPerW,
    const int* __restrict__ bi, const int* __restrict__ ti,
    const float* __restrict__ gs, float* __restrict__ outp)
{
    constexpr int BN  = NI * 32;
    constexpr int BS  = BN + 8;        // B smem row stride
    constexpr int BN4 = BN / 4;
    constexpr int ABUF = 2 * 128 * 36; // uint32 units

    int bm = blockIdx.x;
    int by = blockIdx.y;
    int w  = by / blocksPerW;
    int cb = by % blocksPerW;
    const float* B    = (w == 0) ? B0    : (w == 1) ? B1    : B2;
    const float* bias = (w == 0) ? bias0 : (w == 1) ? bias1 : bias2;
    float*       C    = (w == 0) ? C0    : (w == 1) ? C1    : C2;

    extern __shared__ uint32_t ts[];
    uint32_t sbase = sptr(ts);

    int tid = threadIdx.x;
    int lane = tid & 31;
    int warp = tid >> 5;
    int warpM = warp & 1;
    int warpN = warp >> 1;
    int qr = lane >> 2;
    int qc = lane & 3;

    float acc[4][NI][4];
#pragma unroll
    for (int mi = 0; mi < 4; mi++)
#pragma unroll
        for (int ni = 0; ni < NI; ni++)
#pragma unroll
            for (int j = 0; j < 4; j++) acc[mi][ni][j] = 0.f;

    const float* Ablk = A + (size_t)bm * 128 * K;
    const float* Bblk = B + cb * BN;

    int nk = K >> 5;

    auto issue = [&](int kt, int buf) {
#pragma unroll
        for (int i = 0; i < 4; i++) {
            int idx = tid + 256 * i;
            int row = idx >> 3;
            int c4 = idx & 7;
            cp16(sbase + (buf * 128 * 36 + row * 36 + c4 * 4) * 4,
                 &Ablk[(size_t)row * K + kt * 32 + c4 * 4]);
        }
#pragma unroll
        for (int i = 0; i < NI; i++) {
            int idx = tid + 256 * i;
            int row = idx / BN4;
            int c = idx % BN4;
            cp16(sbase + (ABUF + buf * 32 * BS + row * BS + c * 4) * 4,
                 &Bblk[(size_t)(kt * 32 + row) * ldo + c * 4]);
        }
        cp_commit();
    };

    issue(0, 0);

    for (int kt = 0; kt < nk; kt++) {
        cp_wait<0>();
        __syncthreads();
        if (kt + 1 < nk) issue(kt + 1, (kt + 1) & 1);

        const uint32_t* Ab = ts + (kt & 1) * 128 * 36;
        const uint32_t* Bb = ts + ABUF + (kt & 1) * 32 * BS;
#pragma unroll
        for (int kk = 0; kk < 4; kk++) {
            int k0 = kk * 8;
            uint32_t a[4][4], b[NI][2];
#pragma unroll
            for (int mi = 0; mi < 4; mi++) {
                int r0 = warpM * 64 + mi * 16 + qr;
                a[mi][0] = Ab[r0 * 36 + k0 + qc];
                a[mi][1] = Ab[(r0 + 8) * 36 + k0 + qc];
                a[mi][2] = Ab[r0 * 36 + k0 + qc + 4];
                a[mi][3] = Ab[(r0 + 8) * 36 + k0 + qc + 4];
            }
#pragma unroll
            for (int ni = 0; ni < NI; ni++) {
                int nn = warpN * (NI * 8) + ni * 8 + qr;
                b[ni][0] = Bb[(k0 + qc) * BS + nn];
                b[ni][1] = Bb[(k0 + qc + 4) * BS + nn];
            }
#pragma unroll
            for (int mi = 0; mi < 4; mi++)
#pragma unroll
                for (int ni = 0; ni < NI; ni++)
                    mma_tf32(acc[mi][ni], a[mi], b[ni]);
        }
    }

#pragma unroll
    for (int mi = 0; mi < 4; mi++) {
#pragma unroll
        for (int ni = 0; ni < NI; ni++) {
            int row = bm * 128 + warpM * 64 + mi * 16 + qr;
            int col = cb * BN + warpN * (NI * 8) + ni * 8 + 2 * qc;
            float2 lo, hi;
            lo.x = acc[mi][ni][0]; lo.y = acc[mi][ni][1];
            hi.x = acc[mi][ni][2]; hi.y = acc[mi][ni][3];
            if (bias) {
                float b0 = bias[col], b1 = bias[col + 1];
                lo.x += b0; lo.y += b1; hi.x += b0; hi.y += b1;
            }
            if (res) {
                const float* r0 = res + (size_t)row * ldo + col;
                const float* r1 = res + (size_t)(row + 8) * ldo + col;
                lo.x += r0[0]; lo.y += r0[1];
                hi.x += r1[0]; hi.y += r1[1];
            }
            if (outp) {
                // fused gated scatter: this GEMM's output IS 'processed'
                int r1i = row + 8;
                float g0 = gs[row], g1 = gs[r1i];
                const float* s0 = g_sel + (size_t)row * Dc + col;
                const float* s1 = g_sel + (size_t)r1i * Dc + col;
                float2 o0, o1;
                o0.x = s0[0] + g0 * (lo.x - s0[0]);
                o0.y = s0[1] + g0 * (lo.y - s0[1]);
                o1.x = s1[0] + g1 * (hi.x - s1[0]);
                o1.y = s1[1] + g1 * (hi.y - s1[1]);
                size_t d0 = ((size_t)bi[row] * Sc + ti[row]) * Dc + col;
                size_t d1 = ((size_t)bi[r1i] * Sc + ti[r1i]) * Dc + col;
                *(float2*)&outp[d0] = o0;
                *(float2*)&outp[d1] = o1;
            } else {
                *(float2*)&C[(size_t)row * ldo + col] = lo;
                *(float2*)&C[(size_t)(row + 8) * ldo + col] = hi;
            }
        }
    }
}

#define TG_SMEM_256 ((2*128*36 + 2*32*264) * 4)
#define TG_SMEM_128 ((2*128*36 + 2*32*136) * 4)

// ---------------- RoPE in-place on g_q and g_k ----------------
__global__ __launch_bounds__(256) void rope_kernel()
{
    int idx = blockIdx.x * blockDim.x + threadIdx.x;
    int total = Nc * Hc * 32;
    float* buf = (idx < total) ? g_q : g_k;
    int r = idx % total;
    int n = r / (Hc * 32);
    int rem = r % (Hc * 32);
    int h = rem >> 5;
    int d = rem & 31;
    float c1 = g_cg[n * HDc + d],      s1 = g_sg[n * HDc + d];
    float c2 = g_cg[n * HDc + d + 32], s2 = g_sg[n * HDc + d + 32];
    float* p = buf + (size_t)n * Dc + h * HDc;
    float x1 = p[d], x2 = p[d + 32];
    p[d]      = x1 * c1 - x2 * s1;
    p[d + 32] = x2 * c2 + x1 * s2;
}

// ---------------- fused flash attention (tf32 mma, online softmax) ----------------
// Double-buffered cp.async K/V, ONE __syncthreads per tile.
// Block x = pair i handles q-tiles i and 31-i (uniform 33 k-tiles/block).
#define FK(buf) ((buf) * 4352)
#define FV(buf) (8704 + (buf) * 4608)
#define FQ      17920
#define FLASH_SMEM ((2*64*68 + 2*64*72 + 64*68) * 4)

__global__ __launch_bounds__(128) void flash_kernel()
{
    int pair = blockIdx.x;
    int h = blockIdx.y;
    extern __shared__ uint32_t fsm[];
    uint32_t sbase = sptr(fsm);
    int tid = threadIdx.x;
    int warp = tid >> 5, lane = tid & 31;
    int qr = lane >> 2, qc = lane & 3;
    uint32_t* sQ = fsm + FQ;
    uint32_t* sPw = sQ + warp * 16 * 68;

    auto issue_kv = [&](int kt, int buf) {
#pragma unroll
        for (int i = 0; i < 8; i++) {
            int idx = tid + 128 * i;
            int key = idx >> 4, c4 = idx & 15;
            size_t src = (size_t)(kt * 64 + key) * Dc + h * HDc + c4 * 4;
            cp16(sbase + (FK(buf) + key * 68 + c4 * 4) * 4, &g_k[src]);
            cp16(sbase + (FV(buf) + key * 72 + c4 * 4) * 4, &g_v[src]);
        }
        cp_commit();
    };

#pragma unroll 1
    for (int pass = 0; pass < 2; pass++) {
        int qt = pass ? (31 - pair) : pair;

        __syncthreads();   // previous pass done with smem
        // stage Q tile (64x64), raw fp32 bits
#pragma unroll
        for (int i = 0; i < 8; i++) {
            int idx = tid + 128 * i;
            int row = idx >> 4, c4 = idx & 15;
            uint4 v = *(const uint4*)&g_q[(size_t)(qt * 64 + row) * Dc + h * HDc + c4 * 4];
            *(uint4*)&sQ[row * 68 + c4 * 4] = v;
        }
        __syncthreads();

        uint32_t qa[8][4];
        int r0 = warp * 16 + qr;
#pragma unroll
        for (int kf = 0; kf < 8; kf++) {
            int k0 = kf * 8;
            qa[kf][0] = sQ[r0 * 68 + k0 + qc];
            qa[kf][1] = sQ[(r0 + 8) * 68 + k0 + qc];
            qa[kf][2] = sQ[r0 * 68 + k0 + qc + 4];
            qa[kf][3] = sQ[(r0 + 8) * 68 + k0 + qc + 4];
        }
        __syncthreads();   // all warps got Q frags; sQ free for P reuse

        float m0 = -3e38f, m1 = -3e38f, l0 = 0.f, l1 = 0.f;
        float o[8][4];
#pragma unroll
        for (int ni = 0; ni < 8; ni++)
#pragma unroll
            for (int j = 0; j < 4; j++) o[ni][j] = 0.f;

        int ntiles = qt + 1;
        issue_kv(0, 0);
        for (int kt = 0; kt < ntiles; kt++) {
            cp_wait<0>();
            __syncthreads();
            if (kt + 1 < ntiles) issue_kv(kt + 1, (kt + 1) & 1);
            const uint32_t* sK = fsm + FK(kt & 1);
            const uint32_t* sV = fsm + FV(kt & 1);

            // S = Q K^T
            float s[8][4];
#pragma unroll
            for (int ni = 0; ni < 8; ni++)
#pragma unroll
                for (int j = 0; j < 4; j++) s[ni][j] = 0.f;
#pragma unroll
            for (int kf = 0; kf < 8; kf++) {
                int k0 = kf * 8;
#pragma unroll
                for (int ni = 0; ni < 8; ni++) {
                    uint32_t b[2];
                    b[0] = sK[(8 * ni + qr) * 68 + k0 + qc];
                    b[1] = sK[(8 * ni + qr) * 68 + k0 + qc + 4];
                    mma_tf32(s[ni], qa[kf], b);
                }
            }

            // scale + causal mask (diagonal tile only)
            bool diag = (kt == qt);
            int rl0 = warp * 16 + qr;
            int rl1 = rl0 + 8;
#pragma unroll
            for (int ni = 0; ni < 8; ni++) {
                int cl = 8 * ni + 2 * qc;
                s[ni][0] *= 0.125f; s[ni][1] *= 0.125f;
                s[ni][2] *= 0.125f; s[ni][3] *= 0.125f;
                if (diag) {
                    if (cl     > rl0) s[ni][0] = -1e30f;
                    if (cl + 1 > rl0) s[ni][1] = -1e30f;
                    if (cl     > rl1) s[ni][2] = -1e30f;
                    if (cl + 1 > rl1) s[ni][3] = -1e30f;
                }
            }

            // online softmax
            float mx0 = -3e38f, mx1 = -3e38f;
#pragma unroll
            for (int ni = 0; ni < 8; ni++) {
                mx0 = fmaxf(mx0, fmaxf(s[ni][0], s[ni][1]));
                mx1 = fmaxf(mx1, fmaxf(s[ni][2], s[ni][3]));
            }
            mx0 = fmaxf(mx0, __shfl_xor_sync(0xffffffff, mx0, 1));
            mx0 = fmaxf(mx0, __shfl_xor_sync(0xffffffff, mx0, 2));
            mx1 = fmaxf(mx1, __shfl_xor_sync(0xffffffff, mx1, 1));
            mx1 = fmaxf(mx1, __shfl_xor_sync(0xffffffff, mx1, 2));
            float mn0 = fmaxf(m0, mx0), mn1 = fmaxf(m1, mx1);
            float sc0 = __expf(m0 - mn0), sc1 = __expf(m1 - mn1);
            m0 = mn0; m1 = mn1;
            float rs0 = 0.f, rs1 = 0.f;
#pragma unroll
            for (int ni = 0; ni < 8; ni++) {
                s[ni][0] = __expf(s[ni][0] - mn0);
                s[ni][1] = __expf(s[ni][1] - mn0);
                s[ni][2] = __expf(s[ni][2] - mn1);
                s[ni][3] = __expf(s[ni][3] - mn1);
                rs0 += s[ni][0] + s[ni][1];
                rs1 += s[ni][2] + s[ni][3];
            }
            rs0 += __shfl_xor_sync(0xffffffff, rs0, 1);
            rs0 += __shfl_xor_sync(0xffffffff, rs0, 2);
            rs1 += __shfl_xor_sync(0xffffffff, rs1, 1);
            rs1 += __shfl_xor_sync(0xffffffff, rs1, 2);
            l0 = l0 * sc0 + rs0;
            l1 = l1 * sc1 + rs1;
#pragma unroll
            for (int ni = 0; ni < 8; ni++) {
                o[ni][0] *= sc0; o[ni][1] *= sc0;
                o[ni][2] *= sc1; o[ni][3] *= sc1;
            }

            // store P (raw fp32) to per-warp smem region
#pragma unroll
            for (int ni = 0; ni < 8; ni++) {
                int cl = 8 * ni + 2 * qc;
                sPw[qr * 68 + cl]           = __float_as_uint(s[ni][0]);
                sPw[qr * 68 + cl + 1]       = __float_as_uint(s[ni][1]);
                sPw[(qr + 8) * 68 + cl]     = __float_as_uint(s[ni][2]);
                sPw[(qr + 8) * 68 + cl + 1] = __float_as_uint(s[ni][3]);
            }
            __syncwarp();

            // O += P @ V
#pragma unroll
            for (int kf = 0; kf < 8; kf++) {
                int k0 = kf * 8;
                uint32_t a[4];
                a[0] = sPw[qr * 68 + k0 + qc];
                a[1] = sPw[(qr + 8) * 68 + k0 + qc];
                a[2] = sPw[qr * 68 + k0 + qc + 4];
                a[3] = sPw[(qr + 8) * 68 + k0 + qc + 4];
#pragma unroll
                for (int ni = 0; ni < 8; ni++) {
                    uint32_t b[2];
                    b[0] = sV[(k0 + qc) * 72 + 8 * ni + qr];
                    b[1] = sV[(k0 + qc + 4) * 72 + 8 * ni + qr];
                    mma_tf32(o[ni], a, b);
                }
            }
        }

        // epilogue: normalize and write ctx
        float li0 = 1.f / l0, li1 = 1.f / l1;
        int rg0 = qt * 64 + warp * 16 + qr;
#pragma unroll
        for (int ni = 0; ni < 8; ni++) {
            int col = h * HDc + 8 * ni + 2 * qc;
            float2 lo, hi;
            lo.x = o[ni][0] * li0; lo.y = o[ni][1] * li0;
            hi.x = o[ni][2] * li1; hi.y = o[ni][3] * li1;
            *(float2*)&g_ctx[(size_t)rg0 * Dc + col] = lo;
            *(float2*)&g_ctx[(size_t)(rg0 + 8) * Dc + col] = hi;
        }
    }
}

// ---------------- act = silu(gate) * up, into g_up (float4) ----------------
__global__ __launch_bounds__(256) void silu_kernel()
{
    int idx = blockIdx.x * blockDim.x + threadIdx.x;
    float4 a = ((const float4*)g_gate)[idx];
    float4 u = ((const float4*)g_up)[idx];
    u.x *= a.x / (1.f + __expf(-a.x));
    u.y *= a.y / (1.f + __expf(-a.y));
    u.z *= a.z / (1.f + __expf(-a.z));
    u.w *= a.w / (1.f + __expf(-a.w));
    ((float4*)g_up)[idx] = u;
}

// ---------------- driver ----------------
extern "C" void kernel_launch(void* const* d_in, const int* in_sizes, int n_in,
                              void* d_out, int out_size)
{
    const float* hidden = (const float*)d_in[0];
    const int*   bi     = (const int*)d_in[1];
    const int*   ti     = (const int*)d_in[2];
    const float* gs     = (const float*)d_in[3];
    const float* cosp   = (const float*)d_in[4];
    const float* sinp   = (const float*)d_in[5];
    const float* Wq     = (const float*)d_in[6];
    const float* bq     = (const float*)d_in[7];
    const float* Wk     = (const float*)d_in[8];
    const float* bk     = (const float*)d_in[9];
    const float* Wv     = (const float*)d_in[10];
    const float* bv     = (const float*)d_in[11];
    const float* Wo     = (const float*)d_in[12];
    const float* Wg     = (const float*)d_in[13];
    const float* Wu     = (const float*)d_in[14];
    const float* Wd     = (const float*)d_in[15];
    const float* ln1    = (const float*)d_in[16];
    const float* ln2    = (const float*)d_in[17];
    float* out = (float*)d_out;

    static float *p_sel = nullptr, *p_h = nullptr, *p_q = nullptr, *p_k = nullptr,
                 *p_v = nullptr, *p_ctx = nullptr, *p_h2 = nullptr, *p_m = nullptr,
                 *p_gate = nullptr, *p_up = nullptr;
    static bool inited = false;
    if (!inited) {
        cudaGetSymbolAddress((void**)&p_sel, g_sel);
        cudaGetSymbolAddress((void**)&p_h, g_h);
        cudaGetSymbolAddress((void**)&p_q, g_q);
        cudaGetSymbolAddress((void**)&p_k, g_k);
        cudaGetSymbolAddress((void**)&p_v, g_v);
        cudaGetSymbolAddress((void**)&p_ctx, g_ctx);
        cudaGetSymbolAddress((void**)&p_h2, g_h2);
        cudaGetSymbolAddress((void**)&p_m, g_m);
        cudaGetSymbolAddress((void**)&p_gate, g_gate);
        cudaGetSymbolAddress((void**)&p_up, g_up);
        cudaFuncSetAttribute(flash_kernel,
                             cudaFuncAttributeMaxDynamicSharedMemorySize, FLASH_SMEM);
        cudaFuncSetAttribute(tgemm_kernel<8>,
                             cudaFuncAttributeMaxDynamicSharedMemorySize, TG_SMEM_256);
        cudaFuncSetAttribute(tgemm_kernel<4>,
                             cudaFuncAttributeMaxDynamicSharedMemorySize, TG_SMEM_128);
        inited = true;
    }

    // 1) copy hidden -> out (fused-scatter GEMM overwrites selected rows later)
    copy_kernel<<<(Bc * Sc * Dc / 4) / 256, 256>>>((const float4*)hidden, (float4*)out);

    // 2) gather + rmsnorm(ln1) + cos/sin gather
    gather_norm_kernel<<<Nc, 256>>>(hidden, bi, ti, cosp, sinp, ln1);

    // 3) QKV fused tf32 GEMM: h @ {Wq,Wk,Wv} + bias  (BN=256)
    tgemm_kernel<8><<<dim3(16, 12), 256, TG_SMEM_256>>>(
        p_h, Dc, Wq, Wk, Wv, bq, bk, bv, nullptr, p_q, p_k, p_v, Dc, 4,
        nullptr, nullptr, nullptr, nullptr);

    // 4) RoPE on q and k
    rope_kernel<<<(2 * Nc * Hc * 32) / 256, 256>>>();

    // 5) fused flash attention -> g_ctx
    flash_kernel<<<dim3(16, Hc), 128, FLASH_SMEM>>>();

    // 6) h2 = sel + ctx @ Wo  (BN=128)
    tgemm_kernel<4><<<dim3(16, 8), 256, TG_SMEM_128>>>(
        p_ctx, Dc, Wo, Wo, Wo, nullptr, nullptr, nullptr, p_sel,
        p_h2, p_h2, p_h2, Dc, 8,
        nullptr, nullptr, nullptr, nullptr);

    // 7) m = rmsnorm(h2, ln2)
    rmsnorm2_kernel<<<Nc, 256>>>(ln2);

    // 8) gate/up fused tf32 GEMM: m @ {Wg, Wu}  (BN=256)
    tgemm_kernel<8><<<dim3(16, 32), 256, TG_SMEM_256>>>(
        p_m, Dc, Wg, Wu, Wu, nullptr, nullptr, nullptr, nullptr,
        p_gate, p_up, p_up, Fc, 16,
        nullptr, nullptr, nullptr, nullptr);

    // 9) act = silu(gate) * up  (into g_up)
    silu_kernel<<<(Nc * Fc / 4) / 256, 256>>>();

    // 10) down-proj + residual + fused gated scatter directly into out
    tgemm_kernel<4><<<dim3(16, 8), 256, TG_SMEM_128>>>(
        p_up, Fc, Wd, Wd, Wd, nullptr, nullptr, nullptr, p_h2,
        nullptr, nullptr, nullptr, Dc, 8,
        bi, ti, gs, out);
}

// round 9
// speedup vs baseline: 1.0716x; 1.0716x over previous
#include <cuda_runtime.h>
#include <math.h>
#include <stdint.h>

// Problem constants
#define Bc  4
#define Sc  2048
#define Dc  1024
#define Hc  16
#define HDc 64
#define Fc  4096
#define Nc  2048

// ---------------- scratch (__device__ globals; no cudaMalloc allowed) ----------------
__device__ float g_sel[Nc * Dc];
__device__ float g_h[Nc * Dc];
__device__ float g_cg[Nc * HDc];
__device__ float g_sg[Nc * HDc];
__device__ float g_q[Nc * Dc];
__device__ float g_k[Nc * Dc];
__device__ float g_v[Nc * Dc];
__device__ float g_ctx[Nc * Dc];
__device__ float g_h2[Nc * Dc];
__device__ float g_m[Nc * Dc];
__device__ float g_gate[Nc * Fc];
__device__ float g_up[Nc * Fc];

// ---------------- helpers ----------------
__device__ __forceinline__ uint32_t sptr(const void* p) {
    return (uint32_t)__cvta_generic_to_shared(p);
}
__device__ __forceinline__ void cp16(uint32_t s, const void* g) {
    asm volatile("cp.async.cg.shared.global [%0], [%1], 16;\n" :: "r"(s), "l"(g));
}
__device__ __forceinline__ void cp_commit() { asm volatile("cp.async.commit_group;\n"); }
template<int W> __device__ __forceinline__ void cp_wait() {
    asm volatile("cp.async.wait_group %0;\n" :: "n"(W));
}

// raw fp32 bits fed to tf32 mma: HW truncates mantissa to tf32 precision.
__device__ __forceinline__ void mma_tf32(float* c, const uint32_t* a, const uint32_t* b) {
    asm volatile(
        "mma.sync.aligned.m16n8k8.row.col.f32.tf32.tf32.f32 "
        "{%0,%1,%2,%3}, {%4,%5,%6,%7}, {%8,%9}, {%0,%1,%2,%3};"
        : "+f"(c[0]), "+f"(c[1]), "+f"(c[2]), "+f"(c[3])
        : "r"(a[0]), "r"(a[1]), "r"(a[2]), "r"(a[3]), "r"(b[0]), "r"(b[1]));
}

// ---------------- plain copy: hidden -> out ----------------
__global__ __launch_bounds__(256) void copy_kernel(
    const float4* __restrict__ src, float4* __restrict__ dst)
{
    int i = blockIdx.x * 256 + threadIdx.x;
    dst[i] = src[i];
}

// ---------------- gather + RMSNorm(ln1), plus cos/sin gather ----------------
__global__ __launch_bounds__(256) void gather_norm_kernel(
    const float* __restrict__ hidden, const int* __restrict__ bi,
    const int* __restrict__ ti, const float* __restrict__ cosp,
    const float* __restrict__ sinp, const float* __restrict__ ln1)
{
    int n = blockIdx.x;
    int b = bi[n], t = ti[n];
    const float* row = hidden + ((size_t)b * Sc + t) * Dc;
    float vals[4];
    float local = 0.f;
#pragma unroll
    for (int i = 0; i < 4; i++) {
        float x = row[threadIdx.x + 256 * i];
        vals[i] = x;
        local += x * x;
    }
    __shared__ float red[256];
    red[threadIdx.x] = local;
    __syncthreads();
    for (int s = 128; s > 0; s >>= 1) {
        if (threadIdx.x < s) red[threadIdx.x] += red[threadIdx.x + s];
        __syncthreads();
    }
    float inv = rsqrtf(red[0] / (float)Dc + 1e-6f);
#pragma unroll
    for (int i = 0; i < 4; i++) {
        int d = threadIdx.x + 256 * i;
        g_sel[(size_t)n * Dc + d] = vals[i];
        g_h[(size_t)n * Dc + d] = vals[i] * inv * ln1[d];
    }
    if (threadIdx.x < HDc) {
        size_t src = ((size_t)b * Sc + t) * HDc + threadIdx.x;
        g_cg[n * HDc + threadIdx.x] = cosp[src];
        g_sg[n * HDc + threadIdx.x] = sinp[src];
    }
}

// ---------------- RMSNorm(ln2): g_h2 -> g_m ----------------
__global__ __launch_bounds__(256) void rmsnorm2_kernel(const float* __restrict__ ln2)
{
    int n = blockIdx.x;
    const float* row = g_h2 + (size_t)n * Dc;
    float vals[4];
    float local = 0.f;
#pragma unroll
    for (int i = 0; i < 4; i++) {
        float x = row[threadIdx.x + 256 * i];
        vals[i] = x;
        local += x * x;
    }
    __shared__ float red[256];
    red[threadIdx.x] = local;
    __syncthreads();
    for (int s = 128; s > 0; s >>= 1) {
        if (threadIdx.x < s) red[threadIdx.x] += red[threadIdx.x + s];
        __syncthreads();
    }
    float inv = rsqrtf(red[0] / (float)Dc + 1e-6f);
#pragma unroll
    for (int i = 0; i < 4; i++) {
        int d = threadIdx.x + 256 * i;
        g_m[(size_t)n * Dc + d] = vals[i] * inv * ln2[d];
    }
}

// ---------------- pipelined tf32 GEMM: C_w = A @ B_w (+bias_w) (+res) ----------------
// Block tile 128 x BN (BN = NI*32), BK=32, 256 threads, 8 warps (2x4),
// warp tile 64 x (NI*8). 2-stage cp.async, ONE __syncthreads per K-tile.
// B tile is exactly 256*NI float4 loads -> NI full iterations, no guard.
// Optional fused gated-scatter epilogue (outp != nullptr).
template<int NI>
__global__ __launch_bounds__(256) void tgemm_kernel(
    const float* __restrict__ A, int K,
    const float* __restrict__ B0, const float* __restrict__ B1, const float* __restrict__ B2,
    const float* __restrict__ bias0, const float* __restrict__ bias1, const float* __restrict__ bias2,
    const float* __restrict__ res,
    float* __restrict__ C0, float* __restrict__ C1, float* __restrict__ C2,
    int ldo, int blocksPerW,
    const int* __restrict__ bi, const int* __restrict__ ti,
    const float* __restrict__ gs, float* __restrict__ outp)
{
    constexpr int BN  = NI * 32;
    constexpr int BS  = BN + 8;        // B smem row stride
    constexpr int BN4 = BN / 4;
    constexpr int ABUF = 2 * 128 * 36; // uint32 units

    int bm = blockIdx.x;
    int by = blockIdx.y;
    int w  = by / blocksPerW;
    int cb = by % blocksPerW;
    const float* B    = (w == 0) ? B0    : (w == 1) ? B1    : B2;
    const float* bias = (w == 0) ? bias0 : (w == 1) ? bias1 : bias2;
    float*       C    = (w == 0) ? C0    : (w == 1) ? C1    : C2;

    extern __shared__ uint32_t ts[];
    uint32_t sbase = sptr(ts);

    int tid = threadIdx.x;
    int lane = tid & 31;
    int warp = tid >> 5;
    int warpM = warp & 1;
    int warpN = warp >> 1;
    int qr = lane >> 2;
    int qc = lane & 3;

    float acc[4][NI][4];
#pragma unroll
    for (int mi = 0; mi < 4; mi++)
#pragma unroll
        for (int ni = 0; ni < NI; ni++)
#pragma unroll
            for (int j = 0; j < 4; j++) acc[mi][ni][j] = 0.f;

    const float* Ablk = A + (size_t)bm * 128 * K;
    const float* Bblk = B + cb * BN;

    int nk = K >> 5;

    auto issue = [&](int kt, int buf) {
#pragma unroll
        for (int i = 0; i < 4; i++) {
            int idx = tid + 256 * i;
            int row = idx >> 3;
            int c4 = idx & 7;
            cp16(sbase + (buf * 128 * 36 + row * 36 + c4 * 4) * 4,
                 &Ablk[(size_t)row * K + kt * 32 + c4 * 4]);
        }
#pragma unroll
        for (int i = 0; i < NI; i++) {
            int idx = tid + 256 * i;
            int row = idx / BN4;
            int c = idx % BN4;
            cp16(sbase + (ABUF + buf * 32 * BS + row * BS + c * 4) * 4,
                 &Bblk[(size_t)(kt * 32 + row) * ldo + c * 4]);
        }
        cp_commit();
    };

    issue(0, 0);

    for (int kt = 0; kt < nk; kt++) {
        cp_wait<0>();
        __syncthreads();
        if (kt + 1 < nk) issue(kt + 1, (kt + 1) & 1);

        const uint32_t* Ab = ts + (kt & 1) * 128 * 36;
        const uint32_t* Bb = ts + ABUF + (kt & 1) * 32 * BS;
#pragma unroll
        for (int kk = 0; kk < 4; kk++) {
            int k0 = kk * 8;
            uint32_t a[4][4], b[NI][2];
#pragma unroll
            for (int mi = 0; mi < 4; mi++) {
                int r0 = warpM * 64 + mi * 16 + qr;
                a[mi][0] = Ab[r0 * 36 + k0 + qc];
                a[mi][1] = Ab[(r0 + 8) * 36 + k0 + qc];
                a[mi][2] = Ab[r0 * 36 + k0 + qc + 4];
                a[mi][3] = Ab[(r0 + 8) * 36 + k0 + qc + 4];
            }
#pragma unroll
            for (int ni = 0; ni < NI; ni++) {
                int nn = warpN * (NI * 8) + ni * 8 + qr;
                b[ni][0] = Bb[(k0 + qc) * BS + nn];
                b[ni][1] = Bb[(k0 + qc + 4) * BS + nn];
            }
#pragma unroll
            for (int mi = 0; mi < 4; mi++)
#pragma unroll
                for (int ni = 0; ni < NI; ni++)
                    mma_tf32(acc[mi][ni], a[mi], b[ni]);
        }
    }

#pragma unroll
    for (int mi = 0; mi < 4; mi++) {
#pragma unroll
        for (int ni = 0; ni < NI; ni++) {
            int row = bm * 128 + warpM * 64 + mi * 16 + qr;
            int col = cb * BN + warpN * (NI * 8) + ni * 8 + 2 * qc;
            float2 lo, hi;
            lo.x = acc[mi][ni][0]; lo.y = acc[mi][ni][1];
            hi.x = acc[mi][ni][2]; hi.y = acc[mi][ni][3];
            if (bias) {
                float b0 = bias[col], b1 = bias[col + 1];
                lo.x += b0; lo.y += b1; hi.x += b0; hi.y += b1;
            }
            if (res) {
                const float* r0 = res + (size_t)row * ldo + col;
                const float* r1 = res + (size_t)(row + 8) * ldo + col;
                lo.x += r0[0]; lo.y += r0[1];
                hi.x += r1[0]; hi.y += r1[1];
            }
            if (outp) {
                // fused gated scatter: this GEMM's output IS 'processed'
                int r1i = row + 8;
                float g0 = gs[row], g1 = gs[r1i];
                const float* s0 = g_sel + (size_t)row * Dc + col;
                const float* s1 = g_sel + (size_t)r1i * Dc + col;
                float2 o0, o1;
                o0.x = s0[0] + g0 * (lo.x - s0[0]);
                o0.y = s0[1] + g0 * (lo.y - s0[1]);
                o1.x = s1[0] + g1 * (hi.x - s1[0]);
                o1.y = s1[1] + g1 * (hi.y - s1[1]);
                size_t d0 = ((size_t)bi[row] * Sc + ti[row]) * Dc + col;
                size_t d1 = ((size_t)bi[r1i] * Sc + ti[r1i]) * Dc + col;
                *(float2*)&outp[d0] = o0;
                *(float2*)&outp[d1] = o1;
            } else {
                *(float2*)&C[(size_t)row * ldo + col] = lo;
                *(float2*)&C[(size_t)(row + 8) * ldo + col] = hi;
            }
        }
    }
}

#define TG_SMEM_128 ((2*128*36 + 2*32*136) * 4)
#define TG_SMEM_64  ((2*128*36 + 2*32*72) * 4)

// ---------------- RoPE in-place on g_q and g_k ----------------
__global__ __launch_bounds__(256) void rope_kernel()
{
    int idx = blockIdx.x * blockDim.x + threadIdx.x;
    int total = Nc * Hc * 32;
    float* buf = (idx < total) ? g_q : g_k;
    int r = idx % total;
    int n = r / (Hc * 32);
    int rem = r % (Hc * 32);
    int h = rem >> 5;
    int d = rem & 31;
    float c1 = g_cg[n * HDc + d],      s1 = g_sg[n * HDc + d];
    float c2 = g_cg[n * HDc + d + 32], s2 = g_sg[n * HDc + d + 32];
    float* p = buf + (size_t)n * Dc + h * HDc;
    float x1 = p[d], x2 = p[d + 32];
    p[d]      = x1 * c1 - x2 * s1;
    p[d + 32] = x2 * c2 + x1 * s2;
}

// ---------------- fused flash attention (tf32 mma, online softmax) ----------------
// Double-buffered cp.async K/V, ONE __syncthreads per tile.
#define FK(buf) ((buf) * 4352)
#define FV(buf) (8704 + (buf) * 4608)
#define FQ      17920
#define FLASH_SMEM ((2*64*68 + 2*64*72 + 64*68) * 4)

__global__ __launch_bounds__(128) void flash_kernel()
{
    int pair = blockIdx.x;
    int h = blockIdx.y;
    extern __shared__ uint32_t fsm[];
    uint32_t sbase = sptr(fsm);
    int tid = threadIdx.x;
    int warp = tid >> 5, lane = tid & 31;
    int qr = lane >> 2, qc = lane & 3;
    uint32_t* sQ = fsm + FQ;
    uint32_t* sPw = sQ + warp * 16 * 68;

    auto issue_kv = [&](int kt, int buf) {
#pragma unroll
        for (int i = 0; i < 8; i++) {
            int idx = tid + 128 * i;
            int key = idx >> 4, c4 = idx & 15;
            size_t src = (size_t)(kt * 64 + key) * Dc + h * HDc + c4 * 4;
            cp16(sbase + (FK(buf) + key * 68 + c4 * 4) * 4, &g_k[src]);
            cp16(sbase + (FV(buf) + key * 72 + c4 * 4) * 4, &g_v[src]);
        }
        cp_commit();
    };

#pragma unroll 1
    for (int pass = 0; pass < 2; pass++) {
        int qt = pass ? (31 - pair) : pair;

        __syncthreads();   // previous pass done with smem
#pragma unroll
        for (int i = 0; i < 8; i++) {
            int idx = tid + 128 * i;
            int row = idx >> 4, c4 = idx & 15;
            uint4 v = *(const uint4*)&g_q[(size_t)(qt * 64 + row) * Dc + h * HDc + c4 * 4];
            *(uint4*)&sQ[row * 68 + c4 * 4] = v;
        }
        __syncthreads();

        uint32_t qa[8][4];
        int r0 = warp * 16 + qr;
#pragma unroll
        for (int kf = 0; kf < 8; kf++) {
            int k0 = kf * 8;
            qa[kf][0] = sQ[r0 * 68 + k0 + qc];
            qa[kf][1] = sQ[(r0 + 8) * 68 + k0 + qc];
            qa[kf][2] = sQ[r0 * 68 + k0 + qc + 4];
            qa[kf][3] = sQ[(r0 + 8) * 68 + k0 + qc + 4];
        }
        __syncthreads();   // all warps got Q frags; sQ free for P reuse

        float m0 = -3e38f, m1 = -3e38f, l0 = 0.f, l1 = 0.f;
        float o[8][4];
#pragma unroll
        for (int ni = 0; ni < 8; ni++)
#pragma unroll
            for (int j = 0; j < 4; j++) o[ni][j] = 0.f;

        int ntiles = qt + 1;
        issue_kv(0, 0);
        for (int kt = 0; kt < ntiles; kt++) {
            cp_wait<0>();
            __syncthreads();
            if (kt + 1 < ntiles) issue_kv(kt + 1, (kt + 1) & 1);
            const uint32_t* sK = fsm + FK(kt & 1);
            const uint32_t* sV = fsm + FV(kt & 1);

            // S = Q K^T
            float s[8][4];
#pragma unroll
            for (int ni = 0; ni < 8; ni++)
#pragma unroll
                for (int j = 0; j < 4; j++) s[ni][j] = 0.f;
#pragma unroll
            for (int kf = 0; kf < 8; kf++) {
                int k0 = kf * 8;
#pragma unroll
                for (int ni = 0; ni < 8; ni++) {
                    uint32_t b[2];
                    b[0] = sK[(8 * ni + qr) * 68 + k0 + qc];
                    b[1] = sK[(8 * ni + qr) * 68 + k0 + qc + 4];
                    mma_tf32(s[ni], qa[kf], b);
                }
            }

            // scale + causal mask (diagonal tile only)
            bool diag = (kt == qt);
            int rl0 = warp * 16 + qr;
            int rl1 = rl0 + 8;
#pragma unroll
            for (int ni = 0; ni < 8; ni++) {
                int cl = 8 * ni + 2 * qc;
                s[ni][0] *= 0.125f; s[ni][1] *= 0.125f;
                s[ni][2] *= 0.125f; s[ni][3] *= 0.125f;
                if (diag) {
                    if (cl     > rl0) s[ni][0] = -1e30f;
                    if (cl + 1 > rl0) s[ni][1] = -1e30f;
                    if (cl     > rl1) s[ni][2] = -1e30f;
                    if (cl + 1 > rl1) s[ni][3] = -1e30f;
                }
            }

            // online softmax
            float mx0 = -3e38f, mx1 = -3e38f;
#pragma unroll
            for (int ni = 0; ni < 8; ni++) {
                mx0 = fmaxf(mx0, fmaxf(s[ni][0], s[ni][1]));
                mx1 = fmaxf(mx1, fmaxf(s[ni][2], s[ni][3]));
            }
            mx0 = fmaxf(mx0, __shfl_xor_sync(0xffffffff, mx0, 1));
            mx0 = fmaxf(mx0, __shfl_xor_sync(0xffffffff, mx0, 2));
            mx1 = fmaxf(mx1, __shfl_xor_sync(0xffffffff, mx1, 1));
            mx1 = fmaxf(mx1, __shfl_xor_sync(0xffffffff, mx1, 2));
            float mn0 = fmaxf(m0, mx0), mn1 = fmaxf(m1, mx1);
            float sc0 = __expf(m0 - mn0), sc1 = __expf(m1 - mn1);
            m0 = mn0; m1 = mn1;
            float rs0 = 0.f, rs1 = 0.f;
#pragma unroll
            for (int ni = 0; ni < 8; ni++) {
                s[ni][0] = __expf(s[ni][0] - mn0);
                s[ni][1] = __expf(s[ni][1] - mn0);
                s[ni][2] = __expf(s[ni][2] - mn1);
                s[ni][3] = __expf(s[ni][3] - mn1);
                rs0 += s[ni][0] + s[ni][1];
                rs1 += s[ni][2] + s[ni][3];
            }
            rs0 += __shfl_xor_sync(0xffffffff, rs0, 1);
            rs0 += __shfl_xor_sync(0xffffffff, rs0, 2);
            rs1 += __shfl_xor_sync(0xffffffff, rs1, 1);
            rs1 += __shfl_xor_sync(0xffffffff, rs1, 2);
            l0 = l0 * sc0 + rs0;
            l1 = l1 * sc1 + rs1;
#pragma unroll
            for (int ni = 0; ni < 8; ni++) {
                o[ni][0] *= sc0; o[ni][1] *= sc0;
                o[ni][2] *= sc1; o[ni][3] *= sc1;
            }

            // store P (raw fp32) to per-warp smem region
#pragma unroll
            for (int ni = 0; ni < 8; ni++) {
                int cl = 8 * ni + 2 * qc;
                sPw[qr * 68 + cl]           = __float_as_uint(s[ni][0]);
                sPw[qr * 68 + cl + 1]       = __float_as_uint(s[ni][1]);
                sPw[(qr + 8) * 68 + cl]     = __float_as_uint(s[ni][2]);
                sPw[(qr + 8) * 68 + cl + 1] = __float_as_uint(s[ni][3]);
            }
            __syncwarp();

            // O += P @ V
#pragma unroll
            for (int kf = 0; kf < 8; kf++) {
                int k0 = kf * 8;
                uint32_t a[4];
                a[0] = sPw[qr * 68 + k0 + qc];
                a[1] = sPw[(qr + 8) * 68 + k0 + qc];
                a[2] = sPw[qr * 68 + k0 + qc + 4];
                a[3] = sPw[(qr + 8) * 68 + k0 + qc + 4];
#pragma unroll
                for (int ni = 0; ni < 8; ni++) {
                    uint32_t b[2];
                    b[0] = sV[(k0 + qc) * 72 + 8 * ni + qr];
                    b[1] = sV[(k0 + qc + 4) * 72 + 8 * ni + qr];
                    mma_tf32(o[ni], a, b);
                }
            }
        }

        // epilogue: normalize and write ctx
        float li0 = 1.f / l0, li1 = 1.f / l1;
        int rg0 = qt * 64 + warp * 16 + qr;
#pragma unroll
        for (int ni = 0; ni < 8; ni++) {
            int col = h * HDc + 8 * ni + 2 * qc;
            float2 lo, hi;
            lo.x = o[ni][0] * li0; lo.y = o[ni][1] * li0;
            hi.x = o[ni][2] * li1; hi.y = o[ni][3] * li1;
            *(float2*)&g_ctx[(size_t)rg0 * Dc + col] = lo;
            *(float2*)&g_ctx[(size_t)(rg0 + 8) * Dc + col] = hi;
        }
    }
}

// ---------------- act = silu(gate) * up, into g_up (float4) ----------------
__global__ __launch_bounds__(256) void silu_kernel()
{
    int idx = blockIdx.x * blockDim.x + threadIdx.x;
    float4 a = ((const float4*)g_gate)[idx];
    float4 u = ((const float4*)g_up)[idx];
    u.x *= a.x / (1.f + __expf(-a.x));
    u.y *= a.y / (1.f + __expf(-a.y));
    u.z *= a.z / (1.f + __expf(-a.z));
    u.w *= a.w / (1.f + __expf(-a.w));
    ((float4*)g_up)[idx] = u;
}

// ---------------- driver ----------------
extern "C" void kernel_launch(void* const* d_in, const int* in_sizes, int n_in,
                              void* d_out, int out_size)
{
    const float* hidden = (const float*)d_in[0];
    const int*   bi     = (const int*)d_in[1];
    const int*   ti     = (const int*)d_in[2];
    const float* gs     = (const float*)d_in[3];
    const float* cosp   = (const float*)d_in[4];
    const float* sinp   = (const float*)d_in[5];
    const float* Wq     = (const float*)d_in[6];
    const float* bq     = (const float*)d_in[7];
    const float* Wk     = (const float*)d_in[8];
    const float* bk     = (const float*)d_in[9];
    const float* Wv     = (const float*)d_in[10];
    const float* bv     = (const float*)d_in[11];
    const float* Wo     = (const float*)d_in[12];
    const float* Wg     = (const float*)d_in[13];
    const float* Wu     = (const float*)d_in[14];
    const float* Wd     = (const float*)d_in[15];
    const float* ln1    = (const float*)d_in[16];
    const float* ln2    = (const float*)d_in[17];
    float* out = (float*)d_out;

    static float *p_sel = nullptr, *p_h = nullptr, *p_q = nullptr, *p_k = nullptr,
                 *p_v = nullptr, *p_ctx = nullptr, *p_h2 = nullptr, *p_m = nullptr,
                 *p_gate = nullptr, *p_up = nullptr;
    static bool inited = false;
    if (!inited) {
        cudaGetSymbolAddress((void**)&p_sel, g_sel);
        cudaGetSymbolAddress((void**)&p_h, g_h);
        cudaGetSymbolAddress((void**)&p_q, g_q);
        cudaGetSymbolAddress((void**)&p_k, g_k);
        cudaGetSymbolAddress((void**)&p_v, g_v);
        cudaGetSymbolAddress((void**)&p_ctx, g_ctx);
        cudaGetSymbolAddress((void**)&p_h2, g_h2);
        cudaGetSymbolAddress((void**)&p_m, g_m);
        cudaGetSymbolAddress((void**)&p_gate, g_gate);
        cudaGetSymbolAddress((void**)&p_up, g_up);
        cudaFuncSetAttribute(flash_kernel,
                             cudaFuncAttributeMaxDynamicSharedMemorySize, FLASH_SMEM);
        cudaFuncSetAttribute(tgemm_kernel<4>,
                             cudaFuncAttributeMaxDynamicSharedMemorySize, TG_SMEM_128);
        cudaFuncSetAttribute(tgemm_kernel<2>,
                             cudaFuncAttributeMaxDynamicSharedMemorySize, TG_SMEM_64);
        inited = true;
    }

    // 1) copy hidden -> out (fused-scatter GEMM overwrites selected rows later)
    copy_kernel<<<(Bc * Sc * Dc / 4) / 256, 256>>>((const float4*)hidden, (float4*)out);

    // 2) gather + rmsnorm(ln1) + cos/sin gather
    gather_norm_kernel<<<Nc, 256>>>(hidden, bi, ti, cosp, sinp, ln1);

    // 3) QKV fused tf32 GEMM: h @ {Wq,Wk,Wv} + bias  (BN=128, 384 blocks)
    tgemm_kernel<4><<<dim3(16, 24), 256, TG_SMEM_128>>>(
        p_h, Dc, Wq, Wk, Wv, bq, bk, bv, nullptr, p_q, p_k, p_v, Dc, 8,
        nullptr, nullptr, nullptr, nullptr);

    // 4) RoPE on q and k
    rope_kernel<<<(2 * Nc * Hc * 32) / 256, 256>>>();

    // 5) fused flash attention -> g_ctx
    flash_kernel<<<dim3(16, Hc), 128, FLASH_SMEM>>>();

    // 6) h2 = sel + ctx @ Wo  (BN=64, 256 blocks)
    tgemm_kernel<2><<<dim3(16, 16), 256, TG_SMEM_64>>>(
        p_ctx, Dc, Wo, Wo, Wo, nullptr, nullptr, nullptr, p_sel,
        p_h2, p_h2, p_h2, Dc, 16,
        nullptr, nullptr, nullptr, nullptr);

    // 7) m = rmsnorm(h2, ln2)
    rmsnorm2_kernel<<<Nc, 256>>>(ln2);

    // 8) gate/up fused tf32 GEMM: m @ {Wg, Wu}  (BN=128, 512 blocks)
    tgemm_kernel<4><<<dim3(16, 64), 256, TG_SMEM_128>>>(
        p_m, Dc, Wg, Wu, Wu, nullptr, nullptr, nullptr, nullptr,
        p_gate, p_up, p_up, Fc, 32,
        nullptr, nullptr, nullptr, nullptr);

    // 9) act = silu(gate) * up  (into g_up)
    silu_kernel<<<(Nc * Fc / 4) / 256, 256>>>();

    // 10) down-proj + residual + fused gated scatter into out (BN=64, 256 blocks)
    tgemm_kernel<2><<<dim3(16, 16), 256, TG_SMEM_64>>>(
        p_up, Fc, Wd, Wd, Wd, nullptr, nullptr, nullptr, p_h2,
        nullptr, nullptr, nullptr, Dc, 16,
        bi, ti, gs, out);
}

// round 11
// speedup vs baseline: 1.3816x; 1.2892x over previous
#include <cuda_runtime.h>
#include <cuda_fp16.h>
#include <math.h>
#include <stdint.h>

// Problem constants
#define Bc  4
#define Sc  2048
#define Dc  1024
#define Hc  16
#define HDc 64
#define Fc  4096
#define Nc  2048

// ---------------- scratch (__device__ globals; no cudaMalloc allowed) ----------------
__device__ float g_sel[Nc * Dc];
__device__ float g_cg[Nc * HDc];
__device__ float g_sg[Nc * HDc];
__device__ float g_q[Nc * Dc];
__device__ float g_k[Nc * Dc];
__device__ float g_v[Nc * Dc];
__device__ float g_h2[Nc * Dc];
__device__ float g_gate[Nc * Fc];
__device__ float g_up[Nc * Fc];
// half activations (GEMM A operands)
__device__ __half g_hh[Nc * Dc];
__device__ __half g_mh[Nc * Dc];
__device__ __half g_ctxh[Nc * Dc];
__device__ __half g_acth[Nc * Fc];
// packed half2 weights [K/2][N] (u32 view), 32 MB:
// Wq@0 Wk@512K Wv@1M Wo@1.5M Wg@2M Wu@4M Wd@6M (u32 offsets)
__device__ uint32_t g_wh[8 * 1024 * 1024];

// ---------------- helpers ----------------
__device__ __forceinline__ uint32_t sptr(const void* p) {
    return (uint32_t)__cvta_generic_to_shared(p);
}
__device__ __forceinline__ void cp16(uint32_t s, const void* g) {
    asm volatile("cp.async.cg.shared.global [%0], [%1], 16;\n" :: "r"(s), "l"(g));
}
__device__ __forceinline__ void cp_commit() { asm volatile("cp.async.commit_group;\n"); }
template<int W> __device__ __forceinline__ void cp_wait() {
    asm volatile("cp.async.wait_group %0;\n" :: "n"(W));
}

// tf32 mma (flash attention only; raw fp32 bits, HW truncates)
__device__ __forceinline__ void mma_tf32(float* c, const uint32_t* a, const uint32_t* b) {
    asm volatile(
        "mma.sync.aligned.m16n8k8.row.col.f32.tf32.tf32.f32 "
        "{%0,%1,%2,%3}, {%4,%5,%6,%7}, {%8,%9}, {%0,%1,%2,%3};"
        : "+f"(c[0]), "+f"(c[1]), "+f"(c[2]), "+f"(c[3])
        : "r"(a[0]), "r"(a[1]), "r"(a[2]), "r"(a[3]), "r"(b[0]), "r"(b[1]));
}

// fp16 mma m16n8k16, fp32 accumulate
__device__ __forceinline__ void mma_f16(float* c, const uint32_t* a, const uint32_t* b) {
    asm volatile(
        "mma.sync.aligned.m16n8k16.row.col.f32.f16.f16.f32 "
        "{%0,%1,%2,%3}, {%4,%5,%6,%7}, {%8,%9}, {%0,%1,%2,%3};"
        : "+f"(c[0]), "+f"(c[1]), "+f"(c[2]), "+f"(c[3])
        : "r"(a[0]), "r"(a[1]), "r"(a[2]), "r"(a[3]), "r"(b[0]), "r"(b[1]));
}

// ---------------- plain copy: hidden -> out ----------------
__global__ __launch_bounds__(256) void copy_kernel(
    const float4* __restrict__ src, float4* __restrict__ dst)
{
    int i = blockIdx.x * 256 + threadIdx.x;
    dst[i] = src[i];
}

// ---------------- weight conversion: fp32 [K,N] -> packed half2 [K/2][N] ----------
__global__ __launch_bounds__(256) void wconv_kernel(
    const float* __restrict__ W0, const float* __restrict__ W1,
    const float* __restrict__ W2, const float* __restrict__ W3,
    const float* __restrict__ W4, const float* __restrict__ W5,
    const float* __restrict__ W6)
{
    int mi = blockIdx.y;
    const float* src; uint32_t* dst; int Nd; int cnt;
    switch (mi) {
        case 0: src = W0; dst = g_wh;            Nd = 1024; cnt =  524288; break;
        case 1: src = W1; dst = g_wh +  524288;  Nd = 1024; cnt =  524288; break;
        case 2: src = W2; dst = g_wh + 1048576;  Nd = 1024; cnt =  524288; break;
        case 3: src = W3; dst = g_wh + 1572864;  Nd = 1024; cnt =  524288; break;
        case 4: src = W4; dst = g_wh + 2097152;  Nd = 4096; cnt = 2097152; break;
        case 5: src = W5; dst = g_wh + 4194304;  Nd = 4096; cnt = 2097152; break;
        default: src = W6; dst = g_wh + 6291456; Nd = 1024; cnt = 2097152; break;
    }
    int idx = blockIdx.x * 256 + threadIdx.x;
    if (idx >= cnt) return;
    int kp = idx / Nd;
    int n  = idx - kp * Nd;
    float lo = src[(size_t)(2 * kp) * Nd + n];
    float hi = src[(size_t)(2 * kp + 1) * Nd + n];
    __half2 h = __floats2half2_rn(lo, hi);   // .x (low) = even k
    dst[idx] = *(uint32_t*)&h;
}

// ---------------- gather + RMSNorm(ln1) -> g_hh (half), plus sel/cos/sin --------
__global__ __launch_bounds__(256) void gather_norm_kernel(
    const float* __restrict__ hidden, const int* __restrict__ bi,
    const int* __restrict__ ti, const float* __restrict__ cosp,
    const float* __restrict__ sinp, const float* __restrict__ ln1)
{
    int n = blockIdx.x;
    int b = bi[n], t = ti[n];
    const float* row = hidden + ((size_t)b * Sc + t) * Dc;
    float vals[4];
    float local = 0.f;
#pragma unroll
    for (int i = 0; i < 4; i++) {
        float x = row[threadIdx.x + 256 * i];
        vals[i] = x;
        local += x * x;
    }
    __shared__ float red[256];
    red[threadIdx.x] = local;
    __syncthreads();
    for (int s = 128; s > 0; s >>= 1) {
        if (threadIdx.x < s) red[threadIdx.x] += red[threadIdx.x + s];
        __syncthreads();
    }
    float inv = rsqrtf(red[0] / (float)Dc + 1e-6f);
#pragma unroll
    for (int i = 0; i < 4; i++) {
        int d = threadIdx.x + 256 * i;
        g_sel[(size_t)n * Dc + d] = vals[i];
        g_hh[(size_t)n * Dc + d] = __float2half(vals[i] * inv * ln1[d]);
    }
    if (threadIdx.x < HDc) {
        size_t src = ((size_t)b * Sc + t) * HDc + threadIdx.x;
        g_cg[n * HDc + threadIdx.x] = cosp[src];
        g_sg[n * HDc + threadIdx.x] = sinp[src];
    }
}

// ---------------- RMSNorm(ln2): g_h2 -> g_mh (half) ----------------
__global__ __launch_bounds__(256) void rmsnorm2_kernel(const float* __restrict__ ln2)
{
    int n = blockIdx.x;
    const float* row = g_h2 + (size_t)n * Dc;
    float vals[4];
    float local = 0.f;
#pragma unroll
    for (int i = 0; i < 4; i++) {
        float x = row[threadIdx.x + 256 * i];
        vals[i] = x;
        local += x * x;
    }
    __shared__ float red[256];
    red[threadIdx.x] = local;
    __syncthreads();
    for (int s = 128; s > 0; s >>= 1) {
        if (threadIdx.x < s) red[threadIdx.x] += red[threadIdx.x + s];
        __syncthreads();
    }
    float inv = rsqrtf(red[0] / (float)Dc + 1e-6f);
#pragma unroll
    for (int i = 0; i < 4; i++) {
        int d = threadIdx.x + 256 * i;
        g_mh[(size_t)n * Dc + d] = __float2half(vals[i] * inv * ln2[d]);
    }
}

// ---------------- fp16 tensor GEMM: C_w = A @ B_w (+bias_w) (+res) (+scatter) ----
// A: half [M,K] row-major. B: packed half2 [K/2][N] (u32/elem, pair = k,k+1).
// Block tile 128 x BN (BN = NI*32), BK=32, 256 threads, 8 warps (2x4),
// warp tile 64 x (NI*8), mma m16n8k16. 2-stage cp.async, ONE sync per K-tile.
#define A_ST 20                        // A smem row stride (u32)
template<int NI>
__global__ __launch_bounds__(256) void tg16_kernel(
    const __half* __restrict__ A, int K,
    const uint32_t* __restrict__ B0, const uint32_t* __restrict__ B1,
    const uint32_t* __restrict__ B2,
    const float* __restrict__ bias0, const float* __restrict__ bias1,
    const float* __restrict__ bias2,
    const float* __restrict__ res,
    float* __restrict__ C0, float* __restrict__ C1, float* __restrict__ C2,
    int ldo, int blocksPerW,
    const int* __restrict__ bip, const int* __restrict__ tip,
    const float* __restrict__ gsp, float* __restrict__ outp)
{
    constexpr int BN  = NI * 32;
    constexpr int BSS = BN + 8;        // B smem row stride (u32), BSS%32==8
    constexpr int ABUF = 2 * 128 * A_ST;

    int bm = blockIdx.x;
    int by = blockIdx.y;
    int w  = by / blocksPerW;
    int cb = by % blocksPerW;
    const uint32_t* B = (w == 0) ? B0 : (w == 1) ? B1 : B2;
    const float* bias = (w == 0) ? bias0 : (w == 1) ? bias1 : bias2;
    float*       C    = (w == 0) ? C0 : (w == 1) ? C1 : C2;

    extern __shared__ uint32_t ts[];
    uint32_t sbase = sptr(ts);

    int tid = threadIdx.x;
    int lane = tid & 31;
    int warp = tid >> 5;
    int warpM = warp & 1;
    int warpN = warp >> 1;
    int qr = lane >> 2;
    int qc = lane & 3;

    float acc[4][NI][4];
#pragma unroll
    for (int mi = 0; mi < 4; mi++)
#pragma unroll
        for (int ni = 0; ni < NI; ni++)
#pragma unroll
            for (int j = 0; j < 4; j++) acc[mi][ni][j] = 0.f;

    const __half* Ablk = A + (size_t)bm * 128 * K;
    const uint32_t* Bblk = B + cb * BN;

    int nk = K >> 5;

    auto issue = [&](int kt, int buf) {
        // A tile: 128 rows x 32 halfs = 512 x 16B chunks
#pragma unroll
        for (int i = 0; i < 2; i++) {
            int idx = tid + 256 * i;
            int row = idx >> 2;
            int c4 = idx & 3;
            cp16(sbase + (buf * 128 * A_ST + row * A_ST + c4 * 4) * 4,
                 &Ablk[(size_t)row * K + kt * 32 + c4 * 8]);
        }
        // B tile: 16 kp-rows x BN u32 = (BN/64) x 256 x 16B chunks
#pragma unroll
        for (int i = 0; i < BN / 64; i++) {
            int idx = tid + 256 * i;
            int row = idx / (BN / 4);
            int c = idx % (BN / 4);
            cp16(sbase + (ABUF + buf * 16 * BSS + row * BSS + c * 4) * 4,
                 &Bblk[(size_t)(kt * 16 + row) * ldo + c * 4]);
        }
        cp_commit();
    };

    issue(0, 0);

    for (int kt = 0; kt < nk; kt++) {
        cp_wait<0>();
        __syncthreads();
        if (kt + 1 < nk) issue(kt + 1, (kt + 1) & 1);

        const uint32_t* Ab = ts + (kt & 1) * 128 * A_ST;
        const uint32_t* Bb = ts + ABUF + (kt & 1) * 16 * BSS;
#pragma unroll
        for (int st = 0; st < 2; st++) {
            int j0 = st * 8 + qc;
            uint32_t a[4][4], b[NI][2];
#pragma unroll
            for (int mi = 0; mi < 4; mi++) {
                int r0 = warpM * 64 + mi * 16 + qr;
                a[mi][0] = Ab[r0 * A_ST + j0];
                a[mi][1] = Ab[(r0 + 8) * A_ST + j0];
                a[mi][2] = Ab[r0 * A_ST + j0 + 4];
                a[mi][3] = Ab[(r0 + 8) * A_ST + j0 + 4];
            }
#pragma unroll
            for (int ni = 0; ni < NI; ni++) {
                int nn = warpN * (NI * 8) + ni * 8 + qr;
                b[ni][0] = Bb[j0 * BSS + nn];
                b[ni][1] = Bb[(j0 + 4) * BSS + nn];
            }
#pragma unroll
            for (int mi = 0; mi < 4; mi++)
#pragma unroll
                for (int ni = 0; ni < NI; ni++)
                    mma_f16(acc[mi][ni], a[mi], b[ni]);
        }
    }

#pragma unroll
    for (int mi = 0; mi < 4; mi++) {
#pragma unroll
        for (int ni = 0; ni < NI; ni++) {
            int row = bm * 128 + warpM * 64 + mi * 16 + qr;
            int col = cb * BN + warpN * (NI * 8) + ni * 8 + 2 * qc;
            float2 lo, hi;
            lo.x = acc[mi][ni][0]; lo.y = acc[mi][ni][1];
            hi.x = acc[mi][ni][2]; hi.y = acc[mi][ni][3];
            if (bias) {
                float b0 = bias[col], b1 = bias[col + 1];
                lo.x += b0; lo.y += b1; hi.x += b0; hi.y += b1;
            }
            if (res) {
                const float* r0 = res + (size_t)row * ldo + col;
                const float* r1 = res + (size_t)(row + 8) * ldo + col;
                lo.x += r0[0]; lo.y += r0[1];
                hi.x += r1[0]; hi.y += r1[1];
            }
            if (outp) {
                // fused gated scatter: this GEMM's output IS 'processed'
                int r1i = row + 8;
                float g0 = gsp[row], g1 = gsp[r1i];
                const float* s0 = g_sel + (size_t)row * Dc + col;
                const float* s1 = g_sel + (size_t)r1i * Dc + col;
                float2 o0, o1;
                o0.x = s0[0] + g0 * (lo.x - s0[0]);
                o0.y = s0[1] + g0 * (lo.y - s0[1]);
                o1.x = s1[0] + g1 * (hi.x - s1[0]);
                o1.y = s1[1] + g1 * (hi.y - s1[1]);
                size_t d0 = ((size_t)bip[row] * Sc + tip[row]) * Dc + col;
                size_t d1 = ((size_t)bip[r1i] * Sc + tip[r1i]) * Dc + col;
                *(float2*)&outp[d0] = o0;
                *(float2*)&outp[d1] = o1;
            } else {
                *(float2*)&C[(size_t)row * ldo + col] = lo;
                *(float2*)&C[(size_t)(row + 8) * ldo + col] = hi;
            }
        }
    }
}

#define TG16_SMEM_128 ((2*128*A_ST + 2*16*136) * 4)
#define TG16_SMEM_64  ((2*128*A_ST + 2*16*72) * 4)

// ---------------- RoPE in-place on g_q and g_k ----------------
__global__ __launch_bounds__(256) void rope_kernel()
{
    int idx = blockIdx.x * blockDim.x + threadIdx.x;
    int total = Nc * Hc * 32;
    float* buf = (idx < total) ? g_q : g_k;
    int r = idx % total;
    int n = r / (Hc * 32);
    int rem = r % (Hc * 32);
    int h = rem >> 5;
    int d = rem & 31;
    float c1 = g_cg[n * HDc + d],      s1 = g_sg[n * HDc + d];
    float c2 = g_cg[n * HDc + d + 32], s2 = g_sg[n * HDc + d + 32];
    float* p = buf + (size_t)n * Dc + h * HDc;
    float x1 = p[d], x2 = p[d + 32];
    p[d]      = x1 * c1 - x2 * s1;
    p[d + 32] = x2 * c2 + x1 * s2;
}

// ---------------- fused flash attention (tf32 mma, online softmax) ----------------
// Double-buffered cp.async K/V, ONE __syncthreads per tile. Writes g_ctxh (half).
#define FK(buf) ((buf) * 4352)
#define FV(buf) (8704 + (buf) * 4608)
#define FQ      17920
#define FLASH_SMEM ((2*64*68 + 2*64*72 + 64*68) * 4)

__global__ __launch_bounds__(128) void flash_kernel()
{
    int pair = blockIdx.x;
    int h = blockIdx.y;
    extern __shared__ uint32_t fsm[];
    uint32_t sbase = sptr(fsm);
    int tid = threadIdx.x;
    int warp = tid >> 5, lane = tid & 31;
    int qr = lane >> 2, qc = lane & 3;
    uint32_t* sQ = fsm + FQ;
    uint32_t* sPw = sQ + warp * 16 * 68;

    auto issue_kv = [&](int kt, int buf) {
#pragma unroll
        for (int i = 0; i < 8; i++) {
            int idx = tid + 128 * i;
            int key = idx >> 4, c4 = idx & 15;
            size_t src = (size_t)(kt * 64 + key) * Dc + h * HDc + c4 * 4;
            cp16(sbase + (FK(buf) + key * 68 + c4 * 4) * 4, &g_k[src]);
            cp16(sbase + (FV(buf) + key * 72 + c4 * 4) * 4, &g_v[src]);
        }
        cp_commit();
    };

#pragma unroll 1
    for (int pass = 0; pass < 2; pass++) {
        int qt = pass ? (31 - pair) : pair;

        __syncthreads();
#pragma unroll
        for (int i = 0; i < 8; i++) {
            int idx = tid + 128 * i;
            int row = idx >> 4, c4 = idx & 15;
            uint4 v = *(const uint4*)&g_q[(size_t)(qt * 64 + row) * Dc + h * HDc + c4 * 4];
            *(uint4*)&sQ[row * 68 + c4 * 4] = v;
        }
        __syncthreads();

        uint32_t qa[8][4];
        int r0 = warp * 16 + qr;
#pragma unroll
        for (int kf = 0; kf < 8; kf++) {
            int k0 = kf * 8;
            qa[kf][0] = sQ[r0 * 68 + k0 + qc];
            qa[kf][1] = sQ[(r0 + 8) * 68 + k0 + qc];
            qa[kf][2] = sQ[r0 * 68 + k0 + qc + 4];
            qa[kf][3] = sQ[(r0 + 8) * 68 + k0 + qc + 4];
        }
        __syncthreads();

        float m0 = -3e38f, m1 = -3e38f, l0 = 0.f, l1 = 0.f;
        float o[8][4];
#pragma unroll
        for (int ni = 0; ni < 8; ni++)
#pragma unroll
            for (int j = 0; j < 4; j++) o[ni][j] = 0.f;

        int ntiles = qt + 1;
        issue_kv(0, 0);
        for (int kt = 0; kt < ntiles; kt++) {
            cp_wait<0>();
            __syncthreads();
            if (kt + 1 < ntiles) issue_kv(kt + 1, (kt + 1) & 1);
            const uint32_t* sK = fsm + FK(kt & 1);
            const uint32_t* sV = fsm + FV(kt & 1);

            float s[8][4];
#pragma unroll
            for (int ni = 0; ni < 8; ni++)
#pragma unroll
                for (int j = 0; j < 4; j++) s[ni][j] = 0.f;
#pragma unroll
            for (int kf = 0; kf < 8; kf++) {
                int k0 = kf * 8;
#pragma unroll
                for (int ni = 0; ni < 8; ni++) {
                    uint32_t b[2];
                    b[0] = sK[(8 * ni + qr) * 68 + k0 + qc];
                    b[1] = sK[(8 * ni + qr) * 68 + k0 + qc + 4];
                    mma_tf32(s[ni], qa[kf], b);
                }
            }

            bool diag = (kt == qt);
            int rl0 = warp * 16 + qr;
            int rl1 = rl0 + 8;
#pragma unroll
            for (int ni = 0; ni < 8; ni++) {
                int cl = 8 * ni + 2 * qc;
                s[ni][0] *= 0.125f; s[ni][1] *= 0.125f;
                s[ni][2] *= 0.125f; s[ni][3] *= 0.125f;
                if (diag) {
                    if (cl     > rl0) s[ni][0] = -1e30f;
                    if (cl + 1 > rl0) s[ni][1] = -1e30f;
                    if (cl     > rl1) s[ni][2] = -1e30f;
                    if (cl + 1 > rl1) s[ni][3] = -1e30f;
                }
            }

            float mx0 = -3e38f, mx1 = -3e38f;
#pragma unroll
            for (int ni = 0; ni < 8; ni++) {
                mx0 = fmaxf(mx0, fmaxf(s[ni][0], s[ni][1]));
                mx1 = fmaxf(mx1, fmaxf(s[ni][2], s[ni][3]));
            }
            mx0 = fmaxf(mx0, __shfl_xor_sync(0xffffffff, mx0, 1));
            mx0 = fmaxf(mx0, __shfl_xor_sync(0xffffffff, mx0, 2));
            mx1 = fmaxf(mx1, __shfl_xor_sync(0xffffffff, mx1, 1));
            mx1 = fmaxf(mx1, __shfl_xor_sync(0xffffffff, mx1, 2));
            float mn0 = fmaxf(m0, mx0), mn1 = fmaxf(m1, mx1);
            float sc0 = __expf(m0 - mn0), sc1 = __expf(m1 - mn1);
            m0 = mn0; m1 = mn1;
            float rs0 = 0.f, rs1 = 0.f;
#pragma unroll
            for (int ni = 0; ni < 8; ni++) {
                s[ni][0] = __expf(s[ni][0] - mn0);
                s[ni][1] = __expf(s[ni][1] - mn0);
                s[ni][2] = __expf(s[ni][2] - mn1);
                s[ni][3] = __expf(s[ni][3] - mn1);
                rs0 += s[ni][0] + s[ni][1];
                rs1 += s[ni][2] + s[ni][3];
            }
            rs0 += __shfl_xor_sync(0xffffffff, rs0, 1);
            rs0 += __shfl_xor_sync(0xffffffff, rs0, 2);
            rs1 += __shfl_xor_sync(0xffffffff, rs1, 1);
            rs1 += __shfl_xor_sync(0xffffffff, rs1, 2);
            l0 = l0 * sc0 + rs0;
            l1 = l1 * sc1 + rs1;
#pragma unroll
            for (int ni = 0; ni < 8; ni++) {
                o[ni][0] *= sc0; o[ni][1] *= sc0;
                o[ni][2] *= sc1; o[ni][3] *= sc1;
            }

#pragma unroll
            for (int ni = 0; ni < 8; ni++) {
                int cl = 8 * ni + 2 * qc;
                sPw[qr * 68 + cl]           = __float_as_uint(s[ni][0]);
                sPw[qr * 68 + cl + 1]       = __float_as_uint(s[ni][1]);
                sPw[(qr + 8) * 68 + cl]     = __float_as_uint(s[ni][2]);
                sPw[(qr + 8) * 68 + cl + 1] = __float_as_uint(s[ni][3]);
            }
            __syncwarp();

#pragma unroll
            for (int kf = 0; kf < 8; kf++) {
                int k0 = kf * 8;
                uint32_t a[4];
                a[0] = sPw[qr * 68 + k0 + qc];
                a[1] = sPw[(qr + 8) * 68 + k0 + qc];
                a[2] = sPw[qr * 68 + k0 + qc + 4];
                a[3] = sPw[(qr + 8) * 68 + k0 + qc + 4];
#pragma unroll
                for (int ni = 0; ni < 8; ni++) {
                    uint32_t b[2];
                    b[0] = sV[(k0 + qc) * 72 + 8 * ni + qr];
                    b[1] = sV[(k0 + qc + 4) * 72 + 8 * ni + qr];
                    mma_tf32(o[ni], a, b);
                }
            }
        }

        // epilogue: normalize, write ctx as half2
        float li0 = 1.f / l0, li1 = 1.f / l1;
        int rg0 = qt * 64 + warp * 16 + qr;
#pragma unroll
        for (int ni = 0; ni < 8; ni++) {
            int col = h * HDc + 8 * ni + 2 * qc;
            __half2 hlo = __floats2half2_rn(o[ni][0] * li0, o[ni][1] * li0);
            __half2 hhi = __floats2half2_rn(o[ni][2] * li1, o[ni][3] * li1);
            *(__half2*)&g_ctxh[(size_t)rg0 * Dc + col] = hlo;
            *(__half2*)&g_ctxh[(size_t)(rg0 + 8) * Dc + col] = hhi;
        }
    }
}

// ---------------- act = silu(gate) * up -> g_acth (half), 8 elems/thread --------
__global__ __launch_bounds__(256) void silu_kernel()
{
    int idx = blockIdx.x * blockDim.x + threadIdx.x;
    float4 a0 = ((const float4*)g_gate)[idx * 2];
    float4 a1 = ((const float4*)g_gate)[idx * 2 + 1];
    float4 u0 = ((const float4*)g_up)[idx * 2];
    float4 u1 = ((const float4*)g_up)[idx * 2 + 1];
    float v0 = u0.x * a0.x / (1.f + __expf(-a0.x));
    float v1 = u0.y * a0.y / (1.f + __expf(-a0.y));
    float v2 = u0.z * a0.z / (1.f + __expf(-a0.z));
    float v3 = u0.w * a0.w / (1.f + __expf(-a0.w));
    float v4 = u1.x * a1.x / (1.f + __expf(-a1.x));
    float v5 = u1.y * a1.y / (1.f + __expf(-a1.y));
    float v6 = u1.z * a1.z / (1.f + __expf(-a1.z));
    float v7 = u1.w * a1.w / (1.f + __expf(-a1.w));
    __half2 h0 = __floats2half2_rn(v0, v1);
    __half2 h1 = __floats2half2_rn(v2, v3);
    __half2 h2 = __floats2half2_rn(v4, v5);
    __half2 h3 = __floats2half2_rn(v6, v7);
    uint4 o;
    o.x = *(uint32_t*)&h0; o.y = *(uint32_t*)&h1;
    o.z = *(uint32_t*)&h2; o.w = *(uint32_t*)&h3;
    ((uint4*)g_acth)[idx] = o;
}

// ---------------- driver ----------------
extern "C" void kernel_launch(void* const* d_in, const int* in_sizes, int n_in,
                              void* d_out, int out_size)
{
    const float* hidden = (const float*)d_in[0];
    const int*   bi     = (const int*)d_in[1];
    const int*   ti     = (const int*)d_in[2];
    const float* gs     = (const float*)d_in[3];
    const float* cosp   = (const float*)d_in[4];
    const float* sinp   = (const float*)d_in[5];
    const float* Wq     = (const float*)d_in[6];
    const float* bq     = (const float*)d_in[7];
    const float* Wk     = (const float*)d_in[8];
    const float* bk     = (const float*)d_in[9];
    const float* Wv     = (const float*)d_in[10];
    const float* bv     = (const float*)d_in[11];
    const float* Wo     = (const float*)d_in[12];
    const float* Wg     = (const float*)d_in[13];
    const float* Wu     = (const float*)d_in[14];
    const float* Wd     = (const float*)d_in[15];
    const float* ln1    = (const float*)d_in[16];
    const float* ln2    = (const float*)d_in[17];
    float* out = (float*)d_out;

    static float *p_sel = nullptr, *p_q = nullptr, *p_k = nullptr, *p_v = nullptr,
                 *p_h2 = nullptr, *p_gate = nullptr, *p_up = nullptr;
    static __half *p_hh = nullptr, *p_mh = nullptr, *p_ctxh = nullptr, *p_acth = nullptr;
    static uint32_t *p_wh = nullptr;
    static bool inited = false;
    if (!inited) {
        cudaGetSymbolAddress((void**)&p_sel, g_sel);
        cudaGetSymbolAddress((void**)&p_q, g_q);
        cudaGetSymbolAddress((void**)&p_k, g_k);
        cudaGetSymbolAddress((void**)&p_v, g_v);
        cudaGetSymbolAddress((void**)&p_h2, g_h2);
        cudaGetSymbolAddress((void**)&p_gate, g_gate);
        cudaGetSymbolAddress((void**)&p_up, g_up);
        cudaGetSymbolAddress((void**)&p_hh, g_hh);
        cudaGetSymbolAddress((void**)&p_mh, g_mh);
        cudaGetSymbolAddress((void**)&p_ctxh, g_ctxh);
        cudaGetSymbolAddress((void**)&p_acth, g_acth);
        cudaGetSymbolAddress((void**)&p_wh, g_wh);
        cudaFuncSetAttribute(flash_kernel,
                             cudaFuncAttributeMaxDynamicSharedMemorySize, FLASH_SMEM);
        cudaFuncSetAttribute(tg16_kernel<4>,
                             cudaFuncAttributeMaxDynamicSharedMemorySize, TG16_SMEM_128);
        cudaFuncSetAttribute(tg16_kernel<2>,
                             cudaFuncAttributeMaxDynamicSharedMemorySize, TG16_SMEM_64);
        inited = true;
    }
    uint32_t* WqP = p_wh;
    uint32_t* WkP = p_wh + 524288;
    uint32_t* WvP = p_wh + 1048576;
    uint32_t* WoP = p_wh + 1572864;
    uint32_t* WgP = p_wh + 2097152;
    uint32_t* WuP = p_wh + 4194304;
    uint32_t* WdP = p_wh + 6291456;

    // 1) copy hidden -> out (fused-scatter GEMM overwrites selected rows later)
    copy_kernel<<<(Bc * Sc * Dc / 4) / 256, 256>>>((const float4*)hidden, (float4*)out);

    // 2) convert weights to packed half2
    wconv_kernel<<<dim3(8192, 7), 256>>>(Wq, Wk, Wv, Wo, Wg, Wu, Wd);

    // 3) gather + rmsnorm(ln1) -> g_hh
    gather_norm_kernel<<<Nc, 256>>>(hidden, bi, ti, cosp, sinp, ln1);

    // 4) QKV fused fp16 GEMM: g_hh @ {Wq,Wk,Wv} + bias  (BN=128, 384 blocks)
    tg16_kernel<4><<<dim3(16, 24), 256, TG16_SMEM_128>>>(
        p_hh, Dc, WqP, WkP, WvP, bq, bk, bv, nullptr, p_q, p_k, p_v, Dc, 8,
        nullptr, nullptr, nullptr, nullptr);

    // 5) RoPE on q and k
    rope_kernel<<<(2 * Nc * Hc * 32) / 256, 256>>>();

    // 6) fused flash attention -> g_ctxh
    flash_kernel<<<dim3(16, Hc), 128, FLASH_SMEM>>>();

    // 7) h2 = sel + ctx @ Wo  (BN=64, 256 blocks)
    tg16_kernel<2><<<dim3(16, 16), 256, TG16_SMEM_64>>>(
        p_ctxh, Dc, WoP, WoP, WoP, nullptr, nullptr, nullptr, p_sel,
        p_h2, p_h2, p_h2, Dc, 16,
        nullptr, nullptr, nullptr, nullptr);

    // 8) m = rmsnorm(h2, ln2) -> g_mh
    rmsnorm2_kernel<<<Nc, 256>>>(ln2);

    // 9) gate/up fused fp16 GEMM: g_mh @ {Wg, Wu}  (BN=128, 512 blocks)
    tg16_kernel<4><<<dim3(16, 64), 256, TG16_SMEM_128>>>(
        p_mh, Dc, WgP, WuP, WuP, nullptr, nullptr, nullptr, nullptr,
        p_gate, p_up, p_up, Fc, 32,
        nullptr, nullptr, nullptr, nullptr);

    // 10) act = silu(gate) * up -> g_acth
    silu_kernel<<<(Nc * Fc / 8) / 256, 256>>>();

    // 11) down-proj + residual + fused gated scatter into out (BN=64, 256 blocks)
    tg16_kernel<2><<<dim3(16, 16), 256, TG16_SMEM_64>>>(
        p_acth, Fc, WdP, WdP, WdP, nullptr, nullptr, nullptr, p_h2,
        nullptr, nullptr, nullptr, Dc, 16,
        bi, ti, gs, out);
}

// round 12
// speedup vs baseline: 1.4640x; 1.0596x over previous
#include <cuda_runtime.h>
#include <cuda_fp16.h>
#include <math.h>
#include <stdint.h>

// Problem constants
#define Bc  4
#define Sc  2048
#define Dc  1024
#define Hc  16
#define HDc 64
#define Fc  4096
#define Nc  2048

// ---------------- scratch (__device__ globals; no cudaMalloc allowed) ----------------
__device__ float g_sel[Nc * Dc];
__device__ float g_cg[Nc * HDc];
__device__ float g_sg[Nc * HDc];
__device__ float g_q[Nc * Dc];
__device__ float g_k[Nc * Dc];
__device__ float g_v[Nc * Dc];
__device__ float g_h2[Nc * Dc];
__device__ float g_gate[Nc * Fc];
__device__ float g_up[Nc * Fc];
// half activations (GEMM A operands)
__device__ __half g_hh[Nc * Dc];
__device__ __half g_mh[Nc * Dc];
__device__ __half g_ctxh[Nc * Dc];
__device__ __half g_acth[Nc * Fc];
// half q/k after rope; V packed half2 [kp][1024] (token pairs)
__device__ __half g_qh[Nc * Dc];
__device__ __half g_kh[Nc * Dc];
__device__ uint32_t g_vph[(Nc / 2) * Dc];
// packed half2 weights [K/2][N] (u32 view), 32 MB:
__device__ uint32_t g_wh[8 * 1024 * 1024];

// ---------------- helpers ----------------
__device__ __forceinline__ uint32_t sptr(const void* p) {
    return (uint32_t)__cvta_generic_to_shared(p);
}
__device__ __forceinline__ void cp16(uint32_t s, const void* g) {
    asm volatile("cp.async.cg.shared.global [%0], [%1], 16;\n" :: "r"(s), "l"(g));
}
__device__ __forceinline__ void cp_commit() { asm volatile("cp.async.commit_group;\n"); }
template<int W> __device__ __forceinline__ void cp_wait() {
    asm volatile("cp.async.wait_group %0;\n" :: "n"(W));
}

// fp16 mma m16n8k16, fp32 accumulate
__device__ __forceinline__ void mma_f16(float* c, const uint32_t* a, const uint32_t* b) {
    asm volatile(
        "mma.sync.aligned.m16n8k16.row.col.f32.f16.f16.f32 "
        "{%0,%1,%2,%3}, {%4,%5,%6,%7}, {%8,%9}, {%0,%1,%2,%3};"
        : "+f"(c[0]), "+f"(c[1]), "+f"(c[2]), "+f"(c[3])
        : "r"(a[0]), "r"(a[1]), "r"(a[2]), "r"(a[3]), "r"(b[0]), "r"(b[1]));
}

// ldmatrix x4 (A-operand fragments)
__device__ __forceinline__ void ldsm_x4(uint32_t* r, uint32_t addr) {
    asm volatile("ldmatrix.sync.aligned.m8n8.x4.shared.b16 {%0,%1,%2,%3}, [%4];"
                 : "=r"(r[0]), "=r"(r[1]), "=r"(r[2]), "=r"(r[3]) : "r"(addr));
}

__device__ __forceinline__ uint32_t packh2(float a, float b) {
    __half2 h = __floats2half2_rn(a, b);
    return *(uint32_t*)&h;
}

// ---------------- plain copy: hidden -> out ----------------
__global__ __launch_bounds__(256) void copy_kernel(
    const float4* __restrict__ src, float4* __restrict__ dst)
{
    int i = blockIdx.x * 256 + threadIdx.x;
    dst[i] = src[i];
}

// ---------------- weight conversion: fp32 [K,N] -> packed half2 [K/2][N] ----------
__global__ __launch_bounds__(256) void wconv_kernel(
    const float* __restrict__ W0, const float* __restrict__ W1,
    const float* __restrict__ W2, const float* __restrict__ W3,
    const float* __restrict__ W4, const float* __restrict__ W5,
    const float* __restrict__ W6)
{
    int mi = blockIdx.y;
    const float* src; uint32_t* dst; int Nd; int cnt;
    switch (mi) {
        case 0: src = W0; dst = g_wh;            Nd = 1024; cnt =  524288; break;
        case 1: src = W1; dst = g_wh +  524288;  Nd = 1024; cnt =  524288; break;
        case 2: src = W2; dst = g_wh + 1048576;  Nd = 1024; cnt =  524288; break;
        case 3: src = W3; dst = g_wh + 1572864;  Nd = 1024; cnt =  524288; break;
        case 4: src = W4; dst = g_wh + 2097152;  Nd = 4096; cnt = 2097152; break;
        case 5: src = W5; dst = g_wh + 4194304;  Nd = 4096; cnt = 2097152; break;
        default: src = W6; dst = g_wh + 6291456; Nd = 1024; cnt = 2097152; break;
    }
    int idx = blockIdx.x * 256 + threadIdx.x;
    if (idx >= cnt) return;
    int kp = idx / Nd;
    int n  = idx - kp * Nd;
    dst[idx] = packh2(src[(size_t)(2 * kp) * Nd + n], src[(size_t)(2 * kp + 1) * Nd + n]);
}

// ---------------- gather + RMSNorm(ln1) -> g_hh (half), plus sel/cos/sin --------
__global__ __launch_bounds__(256) void gather_norm_kernel(
    const float* __restrict__ hidden, const int* __restrict__ bi,
    const int* __restrict__ ti, const float* __restrict__ cosp,
    const float* __restrict__ sinp, const float* __restrict__ ln1)
{
    int n = blockIdx.x;
    int b = bi[n], t = ti[n];
    const float* row = hidden + ((size_t)b * Sc + t) * Dc;
    float vals[4];
    float local = 0.f;
#pragma unroll
    for (int i = 0; i < 4; i++) {
        float x = row[threadIdx.x + 256 * i];
        vals[i] = x;
        local += x * x;
    }
    __shared__ float red[256];
    red[threadIdx.x] = local;
    __syncthreads();
    for (int s = 128; s > 0; s >>= 1) {
        if (threadIdx.x < s) red[threadIdx.x] += red[threadIdx.x + s];
        __syncthreads();
    }
    float inv = rsqrtf(red[0] / (float)Dc + 1e-6f);
#pragma unroll
    for (int i = 0; i < 4; i++) {
        int d = threadIdx.x + 256 * i;
        g_sel[(size_t)n * Dc + d] = vals[i];
        g_hh[(size_t)n * Dc + d] = __float2half(vals[i] * inv * ln1[d]);
    }
    if (threadIdx.x < HDc) {
        size_t src = ((size_t)b * Sc + t) * HDc + threadIdx.x;
        g_cg[n * HDc + threadIdx.x] = cosp[src];
        g_sg[n * HDc + threadIdx.x] = sinp[src];
    }
}

// ---------------- RMSNorm(ln2): g_h2 -> g_mh (half) ----------------
__global__ __launch_bounds__(256) void rmsnorm2_kernel(const float* __restrict__ ln2)
{
    int n = blockIdx.x;
    const float* row = g_h2 + (size_t)n * Dc;
    float vals[4];
    float local = 0.f;
#pragma unroll
    for (int i = 0; i < 4; i++) {
        float x = row[threadIdx.x + 256 * i];
        vals[i] = x;
        local += x * x;
    }
    __shared__ float red[256];
    red[threadIdx.x] = local;
    __syncthreads();
    for (int s = 128; s > 0; s >>= 1) {
        if (threadIdx.x < s) red[threadIdx.x] += red[threadIdx.x + s];
        __syncthreads();
    }
    float inv = rsqrtf(red[0] / (float)Dc + 1e-6f);
#pragma unroll
    for (int i = 0; i < 4; i++) {
        int d = threadIdx.x + 256 * i;
        g_mh[(size_t)n * Dc + d] = __float2half(vals[i] * inv * ln2[d]);
    }
}

// ---------------- fp16 tensor GEMM (ldmatrix A): C_w = A @ B_w (+bias/res/scatter)
#define A_ST 20                        // A smem row stride (u32)
template<int NI>
__global__ __launch_bounds__(256) void tg16_kernel(
    const __half* __restrict__ A, int K,
    const uint32_t* __restrict__ B0, const uint32_t* __restrict__ B1,
    const uint32_t* __restrict__ B2,
    const float* __restrict__ bias0, const float* __restrict__ bias1,
    const float* __restrict__ bias2,
    const float* __restrict__ res,
    float* __restrict__ C0, float* __restrict__ C1, float* __restrict__ C2,
    int ldo, int blocksPerW,
    const int* __restrict__ bip, const int* __restrict__ tip,
    const float* __restrict__ gsp, float* __restrict__ outp)
{
    constexpr int BN  = NI * 32;
    constexpr int BSS = BN + 8;
    constexpr int ABUF = 2 * 128 * A_ST;

    int bm = blockIdx.x;
    int by = blockIdx.y;
    int w  = by / blocksPerW;
    int cb = by % blocksPerW;
    const uint32_t* B = (w == 0) ? B0 : (w == 1) ? B1 : B2;
    const float* bias = (w == 0) ? bias0 : (w == 1) ? bias1 : bias2;
    float*       C    = (w == 0) ? C0 : (w == 1) ? C1 : C2;

    extern __shared__ uint32_t ts[];
    uint32_t sbase = sptr(ts);

    int tid = threadIdx.x;
    int lane = tid & 31;
    int warp = tid >> 5;
    int warpM = warp & 1;
    int warpN = warp >> 1;
    int qr = lane >> 2;
    int qc = lane & 3;
    // ldmatrix per-lane source row/col within a 16x16 fragment
    int lr  = (lane & 7) + (((lane >> 3) & 1) << 3);
    int lc4 = ((lane >> 4) & 1) * 4;

    float acc[4][NI][4];
#pragma unroll
    for (int mi = 0; mi < 4; mi++)
#pragma unroll
        for (int ni = 0; ni < NI; ni++)
#pragma unroll
            for (int j = 0; j < 4; j++) acc[mi][ni][j] = 0.f;

    const __half* Ablk = A + (size_t)bm * 128 * K;
    const uint32_t* Bblk = B + cb * BN;

    int nk = K >> 5;

    auto issue = [&](int kt, int buf) {
#pragma unroll
        for (int i = 0; i < 2; i++) {
            int idx = tid + 256 * i;
            int row = idx >> 2;
            int c4 = idx & 3;
            cp16(sbase + (buf * 128 * A_ST + row * A_ST + c4 * 4) * 4,
                 &Ablk[(size_t)row * K + kt * 32 + c4 * 8]);
        }
#pragma unroll
        for (int i = 0; i < BN / 64; i++) {
            int idx = tid + 256 * i;
            int row = idx / (BN / 4);
            int c = idx % (BN / 4);
            cp16(sbase + (ABUF + buf * 16 * BSS + row * BSS + c * 4) * 4,
                 &Bblk[(size_t)(kt * 16 + row) * ldo + c * 4]);
        }
        cp_commit();
    };

    issue(0, 0);

    for (int kt = 0; kt < nk; kt++) {
        cp_wait<0>();
        __syncthreads();
        if (kt + 1 < nk) issue(kt + 1, (kt + 1) & 1);

        uint32_t abase = sbase + ((kt & 1) * 128 * A_ST) * 4;
        const uint32_t* Bb = ts + ABUF + (kt & 1) * 16 * BSS;
#pragma unroll
        for (int st = 0; st < 2; st++) {
            int j0 = st * 8 + qc;
            uint32_t a[4][4], b[NI][2];
#pragma unroll
            for (int mi = 0; mi < 4; mi++) {
                int row = warpM * 64 + mi * 16 + lr;
                ldsm_x4(a[mi], abase + (row * A_ST + st * 8 + lc4) * 4);
            }
#pragma unroll
            for (int ni = 0; ni < NI; ni++) {
                int nn = warpN * (NI * 8) + ni * 8 + qr;
                b[ni][0] = Bb[j0 * BSS + nn];
                b[ni][1] = Bb[(j0 + 4) * BSS + nn];
            }
#pragma unroll
            for (int mi = 0; mi < 4; mi++)
#pragma unroll
                for (int ni = 0; ni < NI; ni++)
                    mma_f16(acc[mi][ni], a[mi], b[ni]);
        }
    }

#pragma unroll
    for (int mi = 0; mi < 4; mi++) {
#pragma unroll
        for (int ni = 0; ni < NI; ni++) {
            int row = bm * 128 + warpM * 64 + mi * 16 + qr;
            int col = cb * BN + warpN * (NI * 8) + ni * 8 + 2 * qc;
            float2 lo, hi;
            lo.x = acc[mi][ni][0]; lo.y = acc[mi][ni][1];
            hi.x = acc[mi][ni][2]; hi.y = acc[mi][ni][3];
            if (bias) {
                float b0 = bias[col], b1 = bias[col + 1];
                lo.x += b0; lo.y += b1; hi.x += b0; hi.y += b1;
            }
            if (res) {
                const float* r0 = res + (size_t)row * ldo + col;
                const float* r1 = res + (size_t)(row + 8) * ldo + col;
                lo.x += r0[0]; lo.y += r0[1];
                hi.x += r1[0]; hi.y += r1[1];
            }
            if (outp) {
                int r1i = row + 8;
                float g0 = gsp[row], g1 = gsp[r1i];
                const float* s0 = g_sel + (size_t)row * Dc + col;
                const float* s1 = g_sel + (size_t)r1i * Dc + col;
                float2 o0, o1;
                o0.x = s0[0] + g0 * (lo.x - s0[0]);
                o0.y = s0[1] + g0 * (lo.y - s0[1]);
                o1.x = s1[0] + g1 * (hi.x - s1[0]);
                o1.y = s1[1] + g1 * (hi.y - s1[1]);
                size_t d0 = ((size_t)bip[row] * Sc + tip[row]) * Dc + col;
                size_t d1 = ((size_t)bip[r1i] * Sc + tip[r1i]) * Dc + col;
                *(float2*)&outp[d0] = o0;
                *(float2*)&outp[d1] = o1;
            } else {
                *(float2*)&C[(size_t)row * ldo + col] = lo;
                *(float2*)&C[(size_t)(row + 8) * ldo + col] = hi;
            }
        }
    }
}

#define TG16_SMEM_128 ((2*128*A_ST + 2*16*136) * 4)
#define TG16_SMEM_64  ((2*128*A_ST + 2*16*72) * 4)

// ---------------- RoPE: g_q/g_k fp32 -> g_qh/g_kh half ----------------
__global__ __launch_bounds__(256) void rope_kernel()
{
    int idx = blockIdx.x * blockDim.x + threadIdx.x;
    int total = Nc * Hc * 32;
    const float* src = (idx < total) ? g_q : g_k;
    __half* dst = (idx < total) ? g_qh : g_kh;
    int r = idx % total;
    int n = r / (Hc * 32);
    int rem = r % (Hc * 32);
    int h = rem >> 5;
    int d = rem & 31;
    float c1 = g_cg[n * HDc + d],      s1 = g_sg[n * HDc + d];
    float c2 = g_cg[n * HDc + d + 32], s2 = g_sg[n * HDc + d + 32];
    const float* p = src + (size_t)n * Dc + h * HDc;
    float x1 = p[d], x2 = p[d + 32];
    __half* q = dst + (size_t)n * Dc + h * HDc;
    q[d]      = __float2half(x1 * c1 - x2 * s1);
    q[d + 32] = __float2half(x2 * c2 + x1 * s2);
}

// ---------------- pack V: g_v fp32 -> g_vph half2 [kp][1024] ----------------
__global__ __launch_bounds__(256) void vpack_kernel()
{
    int idx = blockIdx.x * 256 + threadIdx.x;       // (Nc/2)*Dc
    int kp = idx >> 10;
    int c  = idx & 1023;
    g_vph[idx] = packh2(g_v[(size_t)(2 * kp) * Dc + c],
                        g_v[(size_t)(2 * kp + 1) * Dc + c]);
}

// ---------------- fused flash attention (fp16 m16n8k16, online softmax) ----------
// smem u32 offsets: sK[2] @0,2304 ([64][36]); sV[2] @4608,6912 ([32][72]);
// sQ/sP @9216 ([64][36], per-warp P = warp*16*36)
#define FK2(buf) ((buf) * 2304)
#define FV2(buf) (4608 + (buf) * 2304)
#define FQ2 9216
#define FLASH_SMEM ((2*2304 + 2*2304 + 2304) * 4)

__global__ __launch_bounds__(128) void flash_kernel()
{
    int pair = blockIdx.x;
    int h = blockIdx.y;
    extern __shared__ uint32_t fsm[];
    uint32_t sbase = sptr(fsm);
    int tid = threadIdx.x;
    int warp = tid >> 5, lane = tid & 31;
    int qr = lane >> 2, qc = lane & 3;
    uint32_t* sQ = fsm + FQ2;
    uint32_t* sPw = sQ + warp * 16 * 36;

    auto issue_kv = [&](int kt, int buf) {
        // K: 64 keys x 64 halfs = 512 16B chunks, 4/thread
#pragma unroll
        for (int i = 0; i < 4; i++) {
            int idx = tid + 128 * i;
            int key = idx >> 3, c8 = idx & 7;
            cp16(sbase + (FK2(buf) + key * 36 + c8 * 4) * 4,
                 &g_kh[(size_t)(kt * 64 + key) * Dc + h * HDc + c8 * 8]);
        }
        // V packed: 32 kp-rows x 64 u32 = 512 16B chunks, 4/thread
#pragma unroll
        for (int i = 0; i < 4; i++) {
            int idx = tid + 128 * i;
            int kpl = idx >> 4, c16 = idx & 15;
            cp16(sbase + (FV2(buf) + kpl * 72 + c16 * 4) * 4,
                 &g_vph[(size_t)(kt * 32 + kpl) * Dc + h * HDc + c16 * 4]);
        }
        cp_commit();
    };

#pragma unroll 1
    for (int pass = 0; pass < 2; pass++) {
        int qt = pass ? (31 - pair) : pair;

        __syncthreads();   // previous pass done with smem
        // stage Q tile: 64 rows x 64 halfs = 512 chunks
#pragma unroll
        for (int i = 0; i < 4; i++) {
            int idx = tid + 128 * i;
            int row = idx >> 3, c8 = idx & 7;
            uint4 v = *(const uint4*)&g_qh[(size_t)(qt * 64 + row) * Dc + h * HDc + c8 * 8];
            *(uint4*)&sQ[row * 36 + c8 * 4] = v;
        }
        __syncthreads();

        uint32_t qa[4][4];
        int r0 = warp * 16 + qr;
#pragma unroll
        for (int kf = 0; kf < 4; kf++) {
            qa[kf][0] = sQ[r0 * 36 + 8 * kf + qc];
            qa[kf][1] = sQ[(r0 + 8) * 36 + 8 * kf + qc];
            qa[kf][2] = sQ[r0 * 36 + 8 * kf + 4 + qc];
            qa[kf][3] = sQ[(r0 + 8) * 36 + 8 * kf + 4 + qc];
        }
        __syncthreads();   // Q frags extracted; region reusable for P

        float m0 = -3e38f, m1 = -3e38f, l0 = 0.f, l1 = 0.f;
        float o[8][4];
#pragma unroll
        for (int ni = 0; ni < 8; ni++)
#pragma unroll
            for (int j = 0; j < 4; j++) o[ni][j] = 0.f;

        int ntiles = qt + 1;
        issue_kv(0, 0);
        for (int kt = 0; kt < ntiles; kt++) {
            cp_wait<0>();
            __syncthreads();
            if (kt + 1 < ntiles) issue_kv(kt + 1, (kt + 1) & 1);
            const uint32_t* sK = fsm + FK2(kt & 1);
            const uint32_t* sV = fsm + FV2(kt & 1);

            // S = Q K^T  (fp16)
            float s[8][4];
#pragma unroll
            for (int ni = 0; ni < 8; ni++)
#pragma unroll
                for (int j = 0; j < 4; j++) s[ni][j] = 0.f;
#pragma unroll
            for (int kf = 0; kf < 4; kf++) {
#pragma unroll
                for (int ni = 0; ni < 8; ni++) {
                    uint32_t b[2];
                    b[0] = sK[(8 * ni + qr) * 36 + 8 * kf + qc];
                    b[1] = sK[(8 * ni + qr) * 36 + 8 * kf + 4 + qc];
                    mma_f16(s[ni], qa[kf], b);
                }
            }

            // scale + causal mask (diagonal tile only)
            bool diag = (kt == qt);
            int rl0 = warp * 16 + qr;
            int rl1 = rl0 + 8;
#pragma unroll
            for (int ni = 0; ni < 8; ni++) {
                int cl = 8 * ni + 2 * qc;
                s[ni][0] *= 0.125f; s[ni][1] *= 0.125f;
                s[ni][2] *= 0.125f; s[ni][3] *= 0.125f;
                if (diag) {
                    if (cl     > rl0) s[ni][0] = -1e30f;
                    if (cl + 1 > rl0) s[ni][1] = -1e30f;
                    if (cl     > rl1) s[ni][2] = -1e30f;
                    if (cl + 1 > rl1) s[ni][3] = -1e30f;
                }
            }

            // online softmax
            float mx0 = -3e38f, mx1 = -3e38f;
#pragma unroll
            for (int ni = 0; ni < 8; ni++) {
                mx0 = fmaxf(mx0, fmaxf(s[ni][0], s[ni][1]));
                mx1 = fmaxf(mx1, fmaxf(s[ni][2], s[ni][3]));
            }
            mx0 = fmaxf(mx0, __shfl_xor_sync(0xffffffff, mx0, 1));
            mx0 = fmaxf(mx0, __shfl_xor_sync(0xffffffff, mx0, 2));
            mx1 = fmaxf(mx1, __shfl_xor_sync(0xffffffff, mx1, 1));
            mx1 = fmaxf(mx1, __shfl_xor_sync(0xffffffff, mx1, 2));
            float mn0 = fmaxf(m0, mx0), mn1 = fmaxf(m1, mx1);
            float sc0 = __expf(m0 - mn0), sc1 = __expf(m1 - mn1);
            m0 = mn0; m1 = mn1;
            float rs0 = 0.f, rs1 = 0.f;
#pragma unroll
            for (int ni = 0; ni < 8; ni++) {
                s[ni][0] = __expf(s[ni][0] - mn0);
                s[ni][1] = __expf(s[ni][1] - mn0);
                s[ni][2] = __expf(s[ni][2] - mn1);
                s[ni][3] = __expf(s[ni][3] - mn1);
                rs0 += s[ni][0] + s[ni][1];
                rs1 += s[ni][2] + s[ni][3];
            }
            rs0 += __shfl_xor_sync(0xffffffff, rs0, 1);
            rs0 += __shfl_xor_sync(0xffffffff, rs0, 2);
            rs1 += __shfl_xor_sync(0xffffffff, rs1, 1);
            rs1 += __shfl_xor_sync(0xffffffff, rs1, 2);
            l0 = l0 * sc0 + rs0;
            l1 = l1 * sc1 + rs1;
#pragma unroll
            for (int ni = 0; ni < 8; ni++) {
                o[ni][0] *= sc0; o[ni][1] *= sc0;
                o[ni][2] *= sc1; o[ni][3] *= sc1;
            }

            // store P as half2 (adjacent columns packed along k)
#pragma unroll
            for (int ni = 0; ni < 8; ni++) {
                sPw[qr * 36 + 4 * ni + qc]       = packh2(s[ni][0], s[ni][1]);
                sPw[(qr + 8) * 36 + 4 * ni + qc] = packh2(s[ni][2], s[ni][3]);
            }
            __syncwarp();

            // O += P @ V  (fp16)
#pragma unroll
            for (int kf = 0; kf < 4; kf++) {
                uint32_t a[4];
                a[0] = sPw[qr * 36 + 8 * kf + qc];
                a[1] = sPw[(qr + 8) * 36 + 8 * kf + qc];
                a[2] = sPw[qr * 36 + 8 * kf + 4 + qc];
                a[3] = sPw[(qr + 8) * 36 + 8 * kf + 4 + qc];
#pragma unroll
                for (int ni = 0; ni < 8; ni++) {
                    uint32_t b[2];
                    b[0] = sV[(8 * kf + qc) * 72 + 8 * ni + qr];
                    b[1] = sV[(8 * kf + 4 + qc) * 72 + 8 * ni + qr];
                    mma_f16(o[ni], a, b);
                }
            }
            __syncwarp();
        }

        // epilogue: normalize, write ctx as half2
        float li0 = 1.f / l0, li1 = 1.f / l1;
        int rg0 = qt * 64 + warp * 16 + qr;
#pragma unroll
        for (int ni = 0; ni < 8; ni++) {
            int col = h * HDc + 8 * ni + 2 * qc;
            *(uint32_t*)&g_ctxh[(size_t)rg0 * Dc + col] =
                packh2(o[ni][0] * li0, o[ni][1] * li0);
            *(uint32_t*)&g_ctxh[(size_t)(rg0 + 8) * Dc + col] =
                packh2(o[ni][2] * li1, o[ni][3] * li1);
        }
    }
}

// ---------------- act = silu(gate) * up -> g_acth (half), 8 elems/thread --------
__global__ __launch_bounds__(256) void silu_kernel()
{
    int idx = blockIdx.x * blockDim.x + threadIdx.x;
    float4 a0 = ((const float4*)g_gate)[idx * 2];
    float4 a1 = ((const float4*)g_gate)[idx * 2 + 1];
    float4 u0 = ((const float4*)g_up)[idx * 2];
    float4 u1 = ((const float4*)g_up)[idx * 2 + 1];
    uint4 o;
    o.x = packh2(u0.x * a0.x / (1.f + __expf(-a0.x)),
                 u0.y * a0.y / (1.f + __expf(-a0.y)));
    o.y = packh2(u0.z * a0.z / (1.f + __expf(-a0.z)),
                 u0.w * a0.w / (1.f + __expf(-a0.w)));
    o.z = packh2(u1.x * a1.x / (1.f + __expf(-a1.x)),
                 u1.y * a1.y / (1.f + __expf(-a1.y)));
    o.w = packh2(u1.z * a1.z / (1.f + __expf(-a1.z)),
                 u1.w * a1.w / (1.f + __expf(-a1.w)));
    ((uint4*)g_acth)[idx] = o;
}

// ---------------- driver ----------------
extern "C" void kernel_launch(void* const* d_in, const int* in_sizes, int n_in,
                              void* d_out, int out_size)
{
    const float* hidden = (const float*)d_in[0];
    const int*   bi     = (const int*)d_in[1];
    const int*   ti     = (const int*)d_in[2];
    const float* gs     = (const float*)d_in[3];
    const float* cosp   = (const float*)d_in[4];
    const float* sinp   = (const float*)d_in[5];
    const float* Wq     = (const float*)d_in[6];
    const float* bq     = (const float*)d_in[7];
    const float* Wk     = (const float*)d_in[8];
    const float* bk     = (const float*)d_in[9];
    const float* Wv     = (const float*)d_in[10];
    const float* bv     = (const float*)d_in[11];
    const float* Wo     = (const float*)d_in[12];
    const float* Wg     = (const float*)d_in[13];
    const float* Wu     = (const float*)d_in[14];
    const float* Wd     = (const float*)d_in[15];
    const float* ln1    = (const float*)d_in[16];
    const float* ln2    = (const float*)d_in[17];
    float* out = (float*)d_out;

    static float *p_sel = nullptr, *p_q = nullptr, *p_k = nullptr, *p_v = nullptr,
                 *p_h2 = nullptr, *p_gate = nullptr, *p_up = nullptr;
    static __half *p_hh = nullptr, *p_mh = nullptr, *p_ctxh = nullptr, *p_acth = nullptr;
    static uint32_t *p_wh = nullptr;
    static bool inited = false;
    if (!inited) {
        cudaGetSymbolAddress((void**)&p_sel, g_sel);
        cudaGetSymbolAddress((void**)&p_q, g_q);
        cudaGetSymbolAddress((void**)&p_k, g_k);
        cudaGetSymbolAddress((void**)&p_v, g_v);
        cudaGetSymbolAddress((void**)&p_h2, g_h2);
        cudaGetSymbolAddress((void**)&p_gate, g_gate);
        cudaGetSymbolAddress((void**)&p_up, g_up);
        cudaGetSymbolAddress((void**)&p_hh, g_hh);
        cudaGetSymbolAddress((void**)&p_mh, g_mh);
        cudaGetSymbolAddress((void**)&p_ctxh, g_ctxh);
        cudaGetSymbolAddress((void**)&p_acth, g_acth);
        cudaGetSymbolAddress((void**)&p_wh, g_wh);
        cudaFuncSetAttribute(flash_kernel,
                             cudaFuncAttributeMaxDynamicSharedMemorySize, FLASH_SMEM);
        cudaFuncSetAttribute(tg16_kernel<4>,
                             cudaFuncAttributeMaxDynamicSharedMemorySize, TG16_SMEM_128);
        cudaFuncSetAttribute(tg16_kernel<2>,
                             cudaFuncAttributeMaxDynamicSharedMemorySize, TG16_SMEM_64);
        inited = true;
    }
    uint32_t* WqP = p_wh;
    uint32_t* WkP = p_wh + 524288;
    uint32_t* WvP = p_wh + 1048576;
    uint32_t* WoP = p_wh + 1572864;
    uint32_t* WgP = p_wh + 2097152;
    uint32_t* WuP = p_wh + 4194304;
    uint32_t* WdP = p_wh + 6291456;

    // 1) copy hidden -> out
    copy_kernel<<<(Bc * Sc * Dc / 4) / 256, 256>>>((const float4*)hidden, (float4*)out);

    // 2) convert weights to packed half2
    wconv_kernel<<<dim3(8192, 7), 256>>>(Wq, Wk, Wv, Wo, Wg, Wu, Wd);

    // 3) gather + rmsnorm(ln1) -> g_hh
    gather_norm_kernel<<<Nc, 256>>>(hidden, bi, ti, cosp, sinp, ln1);

    // 4) QKV fused fp16 GEMM  (BN=128, 384 blocks)
    tg16_kernel<4><<<dim3(16, 24), 256, TG16_SMEM_128>>>(
        p_hh, Dc, WqP, WkP, WvP, bq, bk, bv, nullptr, p_q, p_k, p_v, Dc, 8,
        nullptr, nullptr, nullptr, nullptr);

    // 5) RoPE -> g_qh/g_kh (half); pack V -> g_vph
    rope_kernel<<<(2 * Nc * Hc * 32) / 256, 256>>>();
    vpack_kernel<<<(Nc / 2 * Dc) / 256, 256>>>();

    // 6) fused fp16 flash attention -> g_ctxh
    flash_kernel<<<dim3(16, Hc), 128, FLASH_SMEM>>>();

    // 7) h2 = sel + ctx @ Wo  (BN=64, 256 blocks)
    tg16_kernel<2><<<dim3(16, 16), 256, TG16_SMEM_64>>>(
        p_ctxh, Dc, WoP, WoP, WoP, nullptr, nullptr, nullptr, p_sel,
        p_h2, p_h2, p_h2, Dc, 16,
        nullptr, nullptr, nullptr, nullptr);

    // 8) m = rmsnorm(h2, ln2) -> g_mh
    rmsnorm2_kernel<<<Nc, 256>>>(ln2);

    // 9) gate/up fused fp16 GEMM  (BN=128, 512 blocks)
    tg16_kernel<4><<<dim3(16, 64), 256, TG16_SMEM_128>>>(
        p_mh, Dc, WgP, WuP, WuP, nullptr, nullptr, nullptr, nullptr,
        p_gate, p_up, p_up, Fc, 32,
        nullptr, nullptr, nullptr, nullptr);

    // 10) act = silu(gate) * up -> g_acth
    silu_kernel<<<(Nc * Fc / 8) / 256, 256>>>();

    // 11) down-proj + residual + fused gated scatter into out (BN=64, 256 blocks)
    tg16_kernel<2><<<dim3(16, 16), 256, TG16_SMEM_64>>>(
        p_acth, Fc, WdP, WdP, WdP, nullptr, nullptr, nullptr, p_h2,
        nullptr, nullptr, nullptr, Dc, 16,
        bi, ti, gs, out);
}

// round 13
// speedup vs baseline: 1.5492x; 1.0582x over previous
#include <cuda_runtime.h>
#include <cuda_fp16.h>
#include <math.h>
#include <stdint.h>

// Problem constants
#define Bc  4
#define Sc  2048
#define Dc  1024
#define Hc  16
#define HDc 64
#define Fc  4096
#define Nc  2048

// ---------------- scratch (__device__ globals; no cudaMalloc allowed) ----------------
__device__ float g_sel[Nc * Dc];
__device__ float g_cg[Nc * HDc];
__device__ float g_sg[Nc * HDc];
__device__ float g_q[Nc * Dc];
__device__ float g_k[Nc * Dc];
__device__ float g_v[Nc * Dc];
__device__ float g_h2[Nc * Dc];
__device__ float g_gate[Nc * Fc];
__device__ float g_up[Nc * Fc];
// half activations (GEMM A operands)
__device__ __half g_hh[Nc * Dc];
__device__ __half g_mh[Nc * Dc];
__device__ __half g_ctxh[Nc * Dc];
__device__ __half g_acth[Nc * Fc];
// half q/k after rope; V packed half2 [kp][1024] (token pairs)
__device__ __half g_qh[Nc * Dc];
__device__ __half g_kh[Nc * Dc];
__device__ uint32_t g_vph[(Nc / 2) * Dc];
// packed half2 weights [K/2][N] (u32 view), 32 MB:
__device__ uint32_t g_wh[8 * 1024 * 1024];

// ---------------- helpers ----------------
__device__ __forceinline__ uint32_t sptr(const void* p) {
    return (uint32_t)__cvta_generic_to_shared(p);
}
__device__ __forceinline__ void cp16(uint32_t s, const void* g) {
    asm volatile("cp.async.cg.shared.global [%0], [%1], 16;\n" :: "r"(s), "l"(g));
}
__device__ __forceinline__ void cp_commit() { asm volatile("cp.async.commit_group;\n"); }
template<int W> __device__ __forceinline__ void cp_wait() {
    asm volatile("cp.async.wait_group %0;\n" :: "n"(W));
}

// fp16 mma m16n8k16, fp32 accumulate
__device__ __forceinline__ void mma_f16(float* c, const uint32_t* a, const uint32_t* b) {
    asm volatile(
        "mma.sync.aligned.m16n8k16.row.col.f32.f16.f16.f32 "
        "{%0,%1,%2,%3}, {%4,%5,%6,%7}, {%8,%9}, {%0,%1,%2,%3};"
        : "+f"(c[0]), "+f"(c[1]), "+f"(c[2]), "+f"(c[3])
        : "r"(a[0]), "r"(a[1]), "r"(a[2]), "r"(a[3]), "r"(b[0]), "r"(b[1]));
}

// ldmatrix x4 (A-operand fragments)
__device__ __forceinline__ void ldsm_x4(uint32_t* r, uint32_t addr) {
    asm volatile("ldmatrix.sync.aligned.m8n8.x4.shared.b16 {%0,%1,%2,%3}, [%4];"
                 : "=r"(r[0]), "=r"(r[1]), "=r"(r[2]), "=r"(r[3]) : "r"(addr));
}

__device__ __forceinline__ uint32_t packh2(float a, float b) {
    __half2 h = __floats2half2_rn(a, b);
    return *(uint32_t*)&h;
}

// ---------------- plain copy: hidden -> out ----------------
__global__ __launch_bounds__(256) void copy_kernel(
    const float4* __restrict__ src, float4* __restrict__ dst)
{
    int i = blockIdx.x * 256 + threadIdx.x;
    dst[i] = src[i];
}

// ---------------- weight conversion: fp32 [K,N] -> packed half2 [K/2][N] ----------
__global__ __launch_bounds__(256) void wconv_kernel(
    const float* __restrict__ W0, const float* __restrict__ W1,
    const float* __restrict__ W2, const float* __restrict__ W3,
    const float* __restrict__ W4, const float* __restrict__ W5,
    const float* __restrict__ W6)
{
    int mi = blockIdx.y;
    const float* src; uint32_t* dst; int Nd; int cnt;
    switch (mi) {
        case 0: src = W0; dst = g_wh;            Nd = 1024; cnt =  524288; break;
        case 1: src = W1; dst = g_wh +  524288;  Nd = 1024; cnt =  524288; break;
        case 2: src = W2; dst = g_wh + 1048576;  Nd = 1024; cnt =  524288; break;
        case 3: src = W3; dst = g_wh + 1572864;  Nd = 1024; cnt =  524288; break;
        case 4: src = W4; dst = g_wh + 2097152;  Nd = 4096; cnt = 2097152; break;
        case 5: src = W5; dst = g_wh + 4194304;  Nd = 4096; cnt = 2097152; break;
        default: src = W6; dst = g_wh + 6291456; Nd = 1024; cnt = 2097152; break;
    }
    int idx = blockIdx.x * 256 + threadIdx.x;
    if (idx >= cnt) return;
    int kp = idx / Nd;
    int n  = idx - kp * Nd;
    dst[idx] = packh2(src[(size_t)(2 * kp) * Nd + n], src[(size_t)(2 * kp + 1) * Nd + n]);
}

// ---------------- gather + RMSNorm(ln1) -> g_hh (half), plus sel/cos/sin --------
__global__ __launch_bounds__(256) void gather_norm_kernel(
    const float* __restrict__ hidden, const int* __restrict__ bi,
    const int* __restrict__ ti, const float* __restrict__ cosp,
    const float* __restrict__ sinp, const float* __restrict__ ln1)
{
    int n = blockIdx.x;
    int b = bi[n], t = ti[n];
    const float* row = hidden + ((size_t)b * Sc + t) * Dc;
    float vals[4];
    float local = 0.f;
#pragma unroll
    for (int i = 0; i < 4; i++) {
        float x = row[threadIdx.x + 256 * i];
        vals[i] = x;
        local += x * x;
    }
    __shared__ float red[256];
    red[threadIdx.x] = local;
    __syncthreads();
    for (int s = 128; s > 0; s >>= 1) {
        if (threadIdx.x < s) red[threadIdx.x] += red[threadIdx.x + s];
        __syncthreads();
    }
    float inv = rsqrtf(red[0] / (float)Dc + 1e-6f);
#pragma unroll
    for (int i = 0; i < 4; i++) {
        int d = threadIdx.x + 256 * i;
        g_sel[(size_t)n * Dc + d] = vals[i];
        g_hh[(size_t)n * Dc + d] = __float2half(vals[i] * inv * ln1[d]);
    }
    if (threadIdx.x < HDc) {
        size_t src = ((size_t)b * Sc + t) * HDc + threadIdx.x;
        g_cg[n * HDc + threadIdx.x] = cosp[src];
        g_sg[n * HDc + threadIdx.x] = sinp[src];
    }
}

// ---------------- RMSNorm(ln2): g_h2 -> g_mh (half) ----------------
__global__ __launch_bounds__(256) void rmsnorm2_kernel(const float* __restrict__ ln2)
{
    int n = blockIdx.x;
    const float* row = g_h2 + (size_t)n * Dc;
    float vals[4];
    float local = 0.f;
#pragma unroll
    for (int i = 0; i < 4; i++) {
        float x = row[threadIdx.x + 256 * i];
        vals[i] = x;
        local += x * x;
    }
    __shared__ float red[256];
    red[threadIdx.x] = local;
    __syncthreads();
    for (int s = 128; s > 0; s >>= 1) {
        if (threadIdx.x < s) red[threadIdx.x] += red[threadIdx.x + s];
        __syncthreads();
    }
    float inv = rsqrtf(red[0] / (float)Dc + 1e-6f);
#pragma unroll
    for (int i = 0; i < 4; i++) {
        int d = threadIdx.x + 256 * i;
        g_mh[(size_t)n * Dc + d] = __float2half(vals[i] * inv * ln2[d]);
    }
}

// ---------------- fp16 tensor GEMM (ldmatrix A, 3-stage cp.async) ----------------
#define A_ST 20                        // A smem row stride (u32)
template<int NI>
__global__ __launch_bounds__(256) void tg16_kernel(
    const __half* __restrict__ A, int K,
    const uint32_t* __restrict__ B0, const uint32_t* __restrict__ B1,
    const uint32_t* __restrict__ B2,
    const float* __restrict__ bias0, const float* __restrict__ bias1,
    const float* __restrict__ bias2,
    const float* __restrict__ res,
    float* __restrict__ C0, float* __restrict__ C1, float* __restrict__ C2,
    int ldo, int blocksPerW,
    const int* __restrict__ bip, const int* __restrict__ tip,
    const float* __restrict__ gsp, float* __restrict__ outp)
{
    constexpr int BN  = NI * 32;
    constexpr int BSS = BN + 8;
    constexpr int ABUF = 3 * 128 * A_ST;

    int bm = blockIdx.x;
    int by = blockIdx.y;
    int w  = by / blocksPerW;
    int cb = by % blocksPerW;
    const uint32_t* B = (w == 0) ? B0 : (w == 1) ? B1 : B2;
    const float* bias = (w == 0) ? bias0 : (w == 1) ? bias1 : bias2;
    float*       C    = (w == 0) ? C0 : (w == 1) ? C1 : C2;

    extern __shared__ uint32_t ts[];
    uint32_t sbase = sptr(ts);

    int tid = threadIdx.x;
    int lane = tid & 31;
    int warp = tid >> 5;
    int warpM = warp & 1;
    int warpN = warp >> 1;
    int qr = lane >> 2;
    int qc = lane & 3;
    int lr  = (lane & 7) + (((lane >> 3) & 1) << 3);
    int lc4 = ((lane >> 4) & 1) * 4;

    float acc[4][NI][4];
#pragma unroll
    for (int mi = 0; mi < 4; mi++)
#pragma unroll
        for (int ni = 0; ni < NI; ni++)
#pragma unroll
            for (int j = 0; j < 4; j++) acc[mi][ni][j] = 0.f;

    const __half* Ablk = A + (size_t)bm * 128 * K;
    const uint32_t* Bblk = B + cb * BN;

    int nk = K >> 5;

    auto issue = [&](int kt, int buf) {
#pragma unroll
        for (int i = 0; i < 2; i++) {
            int idx = tid + 256 * i;
            int row = idx >> 2;
            int c4 = idx & 3;
            cp16(sbase + (buf * 128 * A_ST + row * A_ST + c4 * 4) * 4,
                 &Ablk[(size_t)row * K + kt * 32 + c4 * 8]);
        }
#pragma unroll
        for (int i = 0; i < BN / 64; i++) {
            int idx = tid + 256 * i;
            int row = idx / (BN / 4);
            int c = idx % (BN / 4);
            cp16(sbase + (ABUF + buf * 16 * BSS + row * BSS + c * 4) * 4,
                 &Bblk[(size_t)(kt * 16 + row) * ldo + c * 4]);
        }
        cp_commit();
    };

    issue(0, 0);
    issue(1, 1);

    for (int kt = 0; kt < nk; kt++) {
        if (kt + 1 < nk) cp_wait<1>(); else cp_wait<0>();
        __syncthreads();
        if (kt + 2 < nk) issue(kt + 2, (kt + 2) % 3);

        int buf = kt % 3;
        uint32_t abase = sbase + (buf * 128 * A_ST) * 4;
        const uint32_t* Bb = ts + ABUF + buf * 16 * BSS;
#pragma unroll
        for (int st = 0; st < 2; st++) {
            int j0 = st * 8 + qc;
            uint32_t a[4][4], b[NI][2];
#pragma unroll
            for (int mi = 0; mi < 4; mi++) {
                int row = warpM * 64 + mi * 16 + lr;
                ldsm_x4(a[mi], abase + (row * A_ST + st * 8 + lc4) * 4);
            }
#pragma unroll
            for (int ni = 0; ni < NI; ni++) {
                int nn = warpN * (NI * 8) + ni * 8 + qr;
                b[ni][0] = Bb[j0 * BSS + nn];
                b[ni][1] = Bb[(j0 + 4) * BSS + nn];
            }
#pragma unroll
            for (int mi = 0; mi < 4; mi++)
#pragma unroll
                for (int ni = 0; ni < NI; ni++)
                    mma_f16(acc[mi][ni], a[mi], b[ni]);
        }
    }

#pragma unroll
    for (int mi = 0; mi < 4; mi++) {
#pragma unroll
        for (int ni = 0; ni < NI; ni++) {
            int row = bm * 128 + warpM * 64 + mi * 16 + qr;
            int col = cb * BN + warpN * (NI * 8) + ni * 8 + 2 * qc;
            float2 lo, hi;
            lo.x = acc[mi][ni][0]; lo.y = acc[mi][ni][1];
            hi.x = acc[mi][ni][2]; hi.y = acc[mi][ni][3];
            if (bias) {
                float b0 = bias[col], b1 = bias[col + 1];
                lo.x += b0; lo.y += b1; hi.x += b0; hi.y += b1;
            }
            if (res) {
                const float* r0 = res + (size_t)row * ldo + col;
                const float* r1 = res + (size_t)(row + 8) * ldo + col;
                lo.x += r0[0]; lo.y += r0[1];
                hi.x += r1[0]; hi.y += r1[1];
            }
            if (outp) {
                int r1i = row + 8;
                float g0 = gsp[row], g1 = gsp[r1i];
                const float* s0 = g_sel + (size_t)row * Dc + col;
                const float* s1 = g_sel + (size_t)r1i * Dc + col;
                float2 o0, o1;
                o0.x = s0[0] + g0 * (lo.x - s0[0]);
                o0.y = s0[1] + g0 * (lo.y - s0[1]);
                o1.x = s1[0] + g1 * (hi.x - s1[0]);
                o1.y = s1[1] + g1 * (hi.y - s1[1]);
                size_t d0 = ((size_t)bip[row] * Sc + tip[row]) * Dc + col;
                size_t d1 = ((size_t)bip[r1i] * Sc + tip[r1i]) * Dc + col;
                *(float2*)&outp[d0] = o0;
                *(float2*)&outp[d1] = o1;
            } else {
                *(float2*)&C[(size_t)row * ldo + col] = lo;
                *(float2*)&C[(size_t)(row + 8) * ldo + col] = hi;
            }
        }
    }
}

#define TG16_SMEM_128 ((3*128*A_ST + 3*16*136) * 4)
#define TG16_SMEM_64  ((3*128*A_ST + 3*16*72) * 4)

// ---------------- RoPE: g_q/g_k fp32 -> g_qh/g_kh half ----------------
__global__ __launch_bounds__(256) void rope_kernel()
{
    int idx = blockIdx.x * blockDim.x + threadIdx.x;
    int total = Nc * Hc * 32;
    const float* src = (idx < total) ? g_q : g_k;
    __half* dst = (idx < total) ? g_qh : g_kh;
    int r = idx % total;
    int n = r / (Hc * 32);
    int rem = r % (Hc * 32);
    int h = rem >> 5;
    int d = rem & 31;
    float c1 = g_cg[n * HDc + d],      s1 = g_sg[n * HDc + d];
    float c2 = g_cg[n * HDc + d + 32], s2 = g_sg[n * HDc + d + 32];
    const float* p = src + (size_t)n * Dc + h * HDc;
    float x1 = p[d], x2 = p[d + 32];
    __half* q = dst + (size_t)n * Dc + h * HDc;
    q[d]      = __float2half(x1 * c1 - x2 * s1);
    q[d + 32] = __float2half(x2 * c2 + x1 * s2);
}

// ---------------- pack V: g_v fp32 -> g_vph half2 [kp][1024] ----------------
__global__ __launch_bounds__(256) void vpack_kernel()
{
    int idx = blockIdx.x * 256 + threadIdx.x;
    int kp = idx >> 10;
    int c  = idx & 1023;
    g_vph[idx] = packh2(g_v[(size_t)(2 * kp) * Dc + c],
                        g_v[(size_t)(2 * kp + 1) * Dc + c]);
}

// ---------------- fused flash attention (fp16 m16n8k16, 3-stage cp.async) --------
// smem u32 offsets: sK[3] @ s*2304; sV[3] @ 6912 + s*2304; sQ/sP @ 13824
#define FK2(buf) ((buf) * 2304)
#define FV2(buf) (6912 + (buf) * 2304)
#define FQ2 13824
#define FLASH_SMEM ((3*2304 + 3*2304 + 2304) * 4)

__global__ __launch_bounds__(128) void flash_kernel()
{
    int pair = blockIdx.x;
    int h = blockIdx.y;
    extern __shared__ uint32_t fsm[];
    uint32_t sbase = sptr(fsm);
    int tid = threadIdx.x;
    int warp = tid >> 5, lane = tid & 31;
    int qr = lane >> 2, qc = lane & 3;
    uint32_t* sQ = fsm + FQ2;
    uint32_t* sPw = sQ + warp * 16 * 36;

    auto issue_kv = [&](int kt, int buf) {
#pragma unroll
        for (int i = 0; i < 4; i++) {
            int idx = tid + 128 * i;
            int key = idx >> 3, c8 = idx & 7;
            cp16(sbase + (FK2(buf) + key * 36 + c8 * 4) * 4,
                 &g_kh[(size_t)(kt * 64 + key) * Dc + h * HDc + c8 * 8]);
        }
#pragma unroll
        for (int i = 0; i < 4; i++) {
            int idx = tid + 128 * i;
            int kpl = idx >> 4, c16 = idx & 15;
            cp16(sbase + (FV2(buf) + kpl * 72 + c16 * 4) * 4,
                 &g_vph[(size_t)(kt * 32 + kpl) * Dc + h * HDc + c16 * 4]);
        }
        cp_commit();
    };

#pragma unroll 1
    for (int pass = 0; pass < 2; pass++) {
        int qt = pass ? (31 - pair) : pair;

        __syncthreads();   // previous pass done with smem
#pragma unroll
        for (int i = 0; i < 4; i++) {
            int idx = tid + 128 * i;
            int row = idx >> 3, c8 = idx & 7;
            uint4 v = *(const uint4*)&g_qh[(size_t)(qt * 64 + row) * Dc + h * HDc + c8 * 8];
            *(uint4*)&sQ[row * 36 + c8 * 4] = v;
        }
        __syncthreads();

        uint32_t qa[4][4];
        int r0 = warp * 16 + qr;
#pragma unroll
        for (int kf = 0; kf < 4; kf++) {
            qa[kf][0] = sQ[r0 * 36 + 8 * kf + qc];
            qa[kf][1] = sQ[(r0 + 8) * 36 + 8 * kf + qc];
            qa[kf][2] = sQ[r0 * 36 + 8 * kf + 4 + qc];
            qa[kf][3] = sQ[(r0 + 8) * 36 + 8 * kf + 4 + qc];
        }
        __syncthreads();   // Q frags extracted; region reusable for P

        float m0 = -3e38f, m1 = -3e38f, l0 = 0.f, l1 = 0.f;
        float o[8][4];
#pragma unroll
        for (int ni = 0; ni < 8; ni++)
#pragma unroll
            for (int j = 0; j < 4; j++) o[ni][j] = 0.f;

        int ntiles = qt + 1;
        issue_kv(0, 0);
        if (ntiles > 1) issue_kv(1, 1);
        for (int kt = 0; kt < ntiles; kt++) {
            if (kt + 1 < ntiles) cp_wait<1>(); else cp_wait<0>();
            __syncthreads();
            if (kt + 2 < ntiles) issue_kv(kt + 2, (kt + 2) % 3);
            const uint32_t* sK = fsm + FK2(kt % 3);
            const uint32_t* sV = fsm + FV2(kt % 3);

            // S = Q K^T  (fp16)
            float s[8][4];
#pragma unroll
            for (int ni = 0; ni < 8; ni++)
#pragma unroll
                for (int j = 0; j < 4; j++) s[ni][j] = 0.f;
#pragma unroll
            for (int kf = 0; kf < 4; kf++) {
#pragma unroll
                for (int ni = 0; ni < 8; ni++) {
                    uint32_t b[2];
                    b[0] = sK[(8 * ni + qr) * 36 + 8 * kf + qc];
                    b[1] = sK[(8 * ni + qr) * 36 + 8 * kf + 4 + qc];
                    mma_f16(s[ni], qa[kf], b);
                }
            }

            // scale + causal mask (diagonal tile only)
            bool diag = (kt == qt);
            int rl0 = warp * 16 + qr;
            int rl1 = rl0 + 8;
#pragma unroll
            for (int ni = 0; ni < 8; ni++) {
                int cl = 8 * ni + 2 * qc;
                s[ni][0] *= 0.125f; s[ni][1] *= 0.125f;
                s[ni][2] *= 0.125f; s[ni][3] *= 0.125f;
                if (diag) {
                    if (cl     > rl0) s[ni][0] = -1e30f;
                    if (cl + 1 > rl0) s[ni][1] = -1e30f;
                    if (cl     > rl1) s[ni][2] = -1e30f;
                    if (cl + 1 > rl1) s[ni][3] = -1e30f;
                }
            }

            // online softmax
            float mx0 = -3e38f, mx1 = -3e38f;
#pragma unroll
            for (int ni = 0; ni < 8; ni++) {
                mx0 = fmaxf(mx0, fmaxf(s[ni][0], s[ni][1]));
                mx1 = fmaxf(mx1, fmaxf(s[ni][2], s[ni][3]));
            }
            mx0 = fmaxf(mx0, __shfl_xor_sync(0xffffffff, mx0, 1));
            mx0 = fmaxf(mx0, __shfl_xor_sync(0xffffffff, mx0, 2));
            mx1 = fmaxf(mx1, __shfl_xor_sync(0xffffffff, mx1, 1));
            mx1 = fmaxf(mx1, __shfl_xor_sync(0xffffffff, mx1, 2));
            float mn0 = fmaxf(m0, mx0), mn1 = fmaxf(m1, mx1);
            float sc0 = __expf(m0 - mn0), sc1 = __expf(m1 - mn1);
            m0 = mn0; m1 = mn1;
            float rs0 = 0.f, rs1 = 0.f;
#pragma unroll
            for (int ni = 0; ni < 8; ni++) {
                s[ni][0] = __expf(s[ni][0] - mn0);
                s[ni][1] = __expf(s[ni][1] - mn0);
                s[ni][2] = __expf(s[ni][2] - mn1);
                s[ni][3] = __expf(s[ni][3] - mn1);
                rs0 += s[ni][0] + s[ni][1];
                rs1 += s[ni][2] + s[ni][3];
            }
            rs0 += __shfl_xor_sync(0xffffffff, rs0, 1);
            rs0 += __shfl_xor_sync(0xffffffff, rs0, 2);
            rs1 += __shfl_xor_sync(0xffffffff, rs1, 1);
            rs1 += __shfl_xor_sync(0xffffffff, rs1, 2);
            l0 = l0 * sc0 + rs0;
            l1 = l1 * sc1 + rs1;
#pragma unroll
            for (int ni = 0; ni < 8; ni++) {
                o[ni][0] *= sc0; o[ni][1] *= sc0;
                o[ni][2] *= sc1; o[ni][3] *= sc1;
            }

            // store P as half2 (adjacent columns packed along k)
#pragma unroll
            for (int ni = 0; ni < 8; ni++) {
                sPw[qr * 36 + 4 * ni + qc]       = packh2(s[ni][0], s[ni][1]);
                sPw[(qr + 8) * 36 + 4 * ni + qc] = packh2(s[ni][2], s[ni][3]);
            }
            __syncwarp();

            // O += P @ V  (fp16)
#pragma unroll
            for (int kf = 0; kf < 4; kf++) {
                uint32_t a[4];
                a[0] = sPw[qr * 36 + 8 * kf + qc];
                a[1] = sPw[(qr + 8) * 36 + 8 * kf + qc];
                a[2] = sPw[qr * 36 + 8 * kf + 4 + qc];
                a[3] = sPw[(qr + 8) * 36 + 8 * kf + 4 + qc];
#pragma unroll
                for (int ni = 0; ni < 8; ni++) {
                    uint32_t b[2];
                    b[0] = sV[(8 * kf + qc) * 72 + 8 * ni + qr];
                    b[1] = sV[(8 * kf + 4 + qc) * 72 + 8 * ni + qr];
                    mma_f16(o[ni], a, b);
                }
            }
            __syncwarp();
        }

        // epilogue: normalize, write ctx as half2
        float li0 = 1.f / l0, li1 = 1.f / l1;
        int rg0 = qt * 64 + warp * 16 + qr;
#pragma unroll
        for (int ni = 0; ni < 8; ni++) {
            int col = h * HDc + 8 * ni + 2 * qc;
            *(uint32_t*)&g_ctxh[(size_t)rg0 * Dc + col] =
                packh2(o[ni][0] * li0, o[ni][1] * li0);
            *(uint32_t*)&g_ctxh[(size_t)(rg0 + 8) * Dc + col] =
                packh2(o[ni][2] * li1, o[ni][3] * li1);
        }
    }
}

// ---------------- act = silu(gate) * up -> g_acth (half), 8 elems/thread --------
__global__ __launch_bounds__(256) void silu_kernel()
{
    int idx = blockIdx.x * blockDim.x + threadIdx.x;
    float4 a0 = ((const float4*)g_gate)[idx * 2];
    float4 a1 = ((const float4*)g_gate)[idx * 2 + 1];
    float4 u0 = ((const float4*)g_up)[idx * 2];
    float4 u1 = ((const float4*)g_up)[idx * 2 + 1];
    uint4 o;
    o.x = packh2(u0.x * a0.x / (1.f + __expf(-a0.x)),
                 u0.y * a0.y / (1.f + __expf(-a0.y)));
    o.y = packh2(u0.z * a0.z / (1.f + __expf(-a0.z)),
                 u0.w * a0.w / (1.f + __expf(-a0.w)));
    o.z = packh2(u1.x * a1.x / (1.f + __expf(-a1.x)),
                 u1.y * a1.y / (1.f + __expf(-a1.y)));
    o.w = packh2(u1.z * a1.z / (1.f + __expf(-a1.z)),
                 u1.w * a1.w / (1.f + __expf(-a1.w)));
    ((uint4*)g_acth)[idx] = o;
}

// ---------------- driver ----------------
extern "C" void kernel_launch(void* const* d_in, const int* in_sizes, int n_in,
                              void* d_out, int out_size)
{
    const float* hidden = (const float*)d_in[0];
    const int*   bi     = (const int*)d_in[1];
    const int*   ti     = (const int*)d_in[2];
    const float* gs     = (const float*)d_in[3];
    const float* cosp   = (const float*)d_in[4];
    const float* sinp   = (const float*)d_in[5];
    const float* Wq     = (const float*)d_in[6];
    const float* bq     = (const float*)d_in[7];
    const float* Wk     = (const float*)d_in[8];
    const float* bk     = (const float*)d_in[9];
    const float* Wv     = (const float*)d_in[10];
    const float* bv     = (const float*)d_in[11];
    const float* Wo     = (const float*)d_in[12];
    const float* Wg     = (const float*)d_in[13];
    const float* Wu     = (const float*)d_in[14];
    const float* Wd     = (const float*)d_in[15];
    const float* ln1    = (const float*)d_in[16];
    const float* ln2    = (const float*)d_in[17];
    float* out = (float*)d_out;

    static float *p_sel = nullptr, *p_q = nullptr, *p_k = nullptr, *p_v = nullptr,
                 *p_h2 = nullptr, *p_gate = nullptr, *p_up = nullptr;
    static __half *p_hh = nullptr, *p_mh = nullptr, *p_ctxh = nullptr, *p_acth = nullptr;
    static uint32_t *p_wh = nullptr;
    static bool inited = false;
    if (!inited) {
        cudaGetSymbolAddress((void**)&p_sel, g_sel);
        cudaGetSymbolAddress((void**)&p_q, g_q);
        cudaGetSymbolAddress((void**)&p_k, g_k);
        cudaGetSymbolAddress((void**)&p_v, g_v);
        cudaGetSymbolAddress((void**)&p_h2, g_h2);
        cudaGetSymbolAddress((void**)&p_gate, g_gate);
        cudaGetSymbolAddress((void**)&p_up, g_up);
        cudaGetSymbolAddress((void**)&p_hh, g_hh);
        cudaGetSymbolAddress((void**)&p_mh, g_mh);
        cudaGetSymbolAddress((void**)&p_ctxh, g_ctxh);
        cudaGetSymbolAddress((void**)&p_acth, g_acth);
        cudaGetSymbolAddress((void**)&p_wh, g_wh);
        cudaFuncSetAttribute(flash_kernel,
                             cudaFuncAttributeMaxDynamicSharedMemorySize, FLASH_SMEM);
        cudaFuncSetAttribute(tg16_kernel<4>,
                             cudaFuncAttributeMaxDynamicSharedMemorySize, TG16_SMEM_128);
        cudaFuncSetAttribute(tg16_kernel<2>,
                             cudaFuncAttributeMaxDynamicSharedMemorySize, TG16_SMEM_64);
        inited = true;
    }
    uint32_t* WqP = p_wh;
    uint32_t* WkP = p_wh + 524288;
    uint32_t* WvP = p_wh + 1048576;
    uint32_t* WoP = p_wh + 1572864;
    uint32_t* WgP = p_wh + 2097152;
    uint32_t* WuP = p_wh + 4194304;
    uint32_t* WdP = p_wh + 6291456;

    // 1) copy hidden -> out
    copy_kernel<<<(Bc * Sc * Dc / 4) / 256, 256>>>((const float4*)hidden, (float4*)out);

    // 2) convert weights to packed half2
    wconv_kernel<<<dim3(8192, 7), 256>>>(Wq, Wk, Wv, Wo, Wg, Wu, Wd);

    // 3) gather + rmsnorm(ln1) -> g_hh
    gather_norm_kernel<<<Nc, 256>>>(hidden, bi, ti, cosp, sinp, ln1);

    // 4) QKV fused fp16 GEMM  (BN=128, 384 blocks)
    tg16_kernel<4><<<dim3(16, 24), 256, TG16_SMEM_128>>>(
        p_hh, Dc, WqP, WkP, WvP, bq, bk, bv, nullptr, p_q, p_k, p_v, Dc, 8,
        nullptr, nullptr, nullptr, nullptr);

    // 5) RoPE -> g_qh/g_kh (half); pack V -> g_vph
    rope_kernel<<<(2 * Nc * Hc * 32) / 256, 256>>>();
    vpack_kernel<<<(Nc / 2 * Dc) / 256, 256>>>();

    // 6) fused fp16 flash attention -> g_ctxh
    flash_kernel<<<dim3(16, Hc), 128, FLASH_SMEM>>>();

    // 7) h2 = sel + ctx @ Wo  (BN=64, 256 blocks)
    tg16_kernel<2><<<dim3(16, 16), 256, TG16_SMEM_64>>>(
        p_ctxh, Dc, WoP, WoP, WoP, nullptr, nullptr, nullptr, p_sel,
        p_h2, p_h2, p_h2, Dc, 16,
        nullptr, nullptr, nullptr, nullptr);

    // 8) m = rmsnorm(h2, ln2) -> g_mh
    rmsnorm2_kernel<<<Nc, 256>>>(ln2);

    // 9) gate/up fused fp16 GEMM  (BN=128, 512 blocks)
    tg16_kernel<4><<<dim3(16, 64), 256, TG16_SMEM_128>>>(
        p_mh, Dc, WgP, WuP, WuP, nullptr, nullptr, nullptr, nullptr,
        p_gate, p_up, p_up, Fc, 32,
        nullptr, nullptr, nullptr, nullptr);

    // 10) act = silu(gate) * up -> g_acth
    silu_kernel<<<(Nc * Fc / 8) / 256, 256>>>();

    // 11) down-proj + residual + fused gated scatter into out (BN=64, 256 blocks)
    tg16_kernel<2><<<dim3(16, 16), 256, TG16_SMEM_64>>>(
        p_acth, Fc, WdP, WdP, WdP, nullptr, nullptr, nullptr, p_h2,
        nullptr, nullptr, nullptr, Dc, 16,
        bi, ti, gs, out);
}

// round 14
// speedup vs baseline: 1.5679x; 1.0121x over previous
#include <cuda_runtime.h>
#include <cuda_fp16.h>
#include <math.h>
#include <stdint.h>

// Problem constants
#define Bc  4
#define Sc  2048
#define Dc  1024
#define Hc  16
#define HDc 64
#define Fc  4096
#define Nc  2048

// ---------------- scratch (__device__ globals; no cudaMalloc allowed) ----------------
__device__ float g_sel[Nc * Dc];
__device__ float g_cg[Nc * HDc];
__device__ float g_sg[Nc * HDc];
__device__ float g_q[Nc * Dc];
__device__ float g_k[Nc * Dc];
__device__ float g_v[Nc * Dc];
__device__ float g_h2[Nc * Dc];
// half activations (GEMM A operands)
__device__ __half g_hh[Nc * Dc];
__device__ __half g_mh[Nc * Dc];
__device__ __half g_ctxh[Nc * Dc];
__device__ __half g_acth[Nc * Fc];
// half q/k after rope; V packed half2 [kp][1024] (token pairs)
__device__ __half g_qh[Nc * Dc];
__device__ __half g_kh[Nc * Dc];
__device__ uint32_t g_vph[(Nc / 2) * Dc];
// packed half2 weights [K/2][N] (u32 view), 32 MB:
__device__ uint32_t g_wh[8 * 1024 * 1024];

// ---------------- helpers ----------------
__device__ __forceinline__ uint32_t sptr(const void* p) {
    return (uint32_t)__cvta_generic_to_shared(p);
}
__device__ __forceinline__ void cp16(uint32_t s, const void* g) {
    asm volatile("cp.async.cg.shared.global [%0], [%1], 16;\n" :: "r"(s), "l"(g));
}
__device__ __forceinline__ void cp_commit() { asm volatile("cp.async.commit_group;\n"); }
template<int W> __device__ __forceinline__ void cp_wait() {
    asm volatile("cp.async.wait_group %0;\n" :: "n"(W));
}

// fp16 mma m16n8k16, fp32 accumulate
__device__ __forceinline__ void mma_f16(float* c, const uint32_t* a, const uint32_t* b) {
    asm volatile(
        "mma.sync.aligned.m16n8k16.row.col.f32.f16.f16.f32 "
        "{%0,%1,%2,%3}, {%4,%5,%6,%7}, {%8,%9}, {%0,%1,%2,%3};"
        : "+f"(c[0]), "+f"(c[1]), "+f"(c[2]), "+f"(c[3])
        : "r"(a[0]), "r"(a[1]), "r"(a[2]), "r"(a[3]), "r"(b[0]), "r"(b[1]));
}

// ldmatrix x4 (A-operand fragments)
__device__ __forceinline__ void ldsm_x4(uint32_t* r, uint32_t addr) {
    asm volatile("ldmatrix.sync.aligned.m8n8.x4.shared.b16 {%0,%1,%2,%3}, [%4];"
                 : "=r"(r[0]), "=r"(r[1]), "=r"(r[2]), "=r"(r[3]) : "r"(addr));
}

__device__ __forceinline__ uint32_t packh2(float a, float b) {
    __half2 h = __floats2half2_rn(a, b);
    return *(uint32_t*)&h;
}

__device__ __forceinline__ float siluf(float x) {
    return x / (1.f + __expf(-x));
}

// ---------------- plain copy: hidden -> out ----------------
__global__ __launch_bounds__(256) void copy_kernel(
    const float4* __restrict__ src, float4* __restrict__ dst)
{
    int i = blockIdx.x * 256 + threadIdx.x;
    dst[i] = src[i];
}

// ---------------- weight conversion: fp32 [K,N] -> packed half2 [K/2][N] ----------
__global__ __launch_bounds__(256) void wconv_kernel(
    const float* __restrict__ W0, const float* __restrict__ W1,
    const float* __restrict__ W2, const float* __restrict__ W3,
    const float* __restrict__ W4, const float* __restrict__ W5,
    const float* __restrict__ W6)
{
    int mi = blockIdx.y;
    const float* src; uint32_t* dst; int Nd; int cnt;
    switch (mi) {
        case 0: src = W0; dst = g_wh;            Nd = 1024; cnt =  524288; break;
        case 1: src = W1; dst = g_wh +  524288;  Nd = 1024; cnt =  524288; break;
        case 2: src = W2; dst = g_wh + 1048576;  Nd = 1024; cnt =  524288; break;
        case 3: src = W3; dst = g_wh + 1572864;  Nd = 1024; cnt =  524288; break;
        case 4: src = W4; dst = g_wh + 2097152;  Nd = 4096; cnt = 2097152; break;
        case 5: src = W5; dst = g_wh + 4194304;  Nd = 4096; cnt = 2097152; break;
        default: src = W6; dst = g_wh + 6291456; Nd = 1024; cnt = 2097152; break;
    }
    int idx = blockIdx.x * 256 + threadIdx.x;
    if (idx >= cnt) return;
    int kp = idx / Nd;
    int n  = idx - kp * Nd;
    dst[idx] = packh2(src[(size_t)(2 * kp) * Nd + n], src[(size_t)(2 * kp + 1) * Nd + n]);
}

// ---------------- gather + RMSNorm(ln1) -> g_hh (half), plus sel/cos/sin --------
__global__ __launch_bounds__(256) void gather_norm_kernel(
    const float* __restrict__ hidden, const int* __restrict__ bi,
    const int* __restrict__ ti, const float* __restrict__ cosp,
    const float* __restrict__ sinp, const float* __restrict__ ln1)
{
    int n = blockIdx.x;
    int b = bi[n], t = ti[n];
    const float* row = hidden + ((size_t)b * Sc + t) * Dc;
    float vals[4];
    float local = 0.f;
#pragma unroll
    for (int i = 0; i < 4; i++) {
        float x = row[threadIdx.x + 256 * i];
        vals[i] = x;
        local += x * x;
    }
    __shared__ float red[256];
    red[threadIdx.x] = local;
    __syncthreads();
    for (int s = 128; s > 0; s >>= 1) {
        if (threadIdx.x < s) red[threadIdx.x] += red[threadIdx.x + s];
        __syncthreads();
    }
    float inv = rsqrtf(red[0] / (float)Dc + 1e-6f);
#pragma unroll
    for (int i = 0; i < 4; i++) {
        int d = threadIdx.x + 256 * i;
        g_sel[(size_t)n * Dc + d] = vals[i];
        g_hh[(size_t)n * Dc + d] = __float2half(vals[i] * inv * ln1[d]);
    }
    if (threadIdx.x < HDc) {
        size_t src = ((size_t)b * Sc + t) * HDc + threadIdx.x;
        g_cg[n * HDc + threadIdx.x] = cosp[src];
        g_sg[n * HDc + threadIdx.x] = sinp[src];
    }
}

// ---------------- RMSNorm(ln2): g_h2 -> g_mh (half) ----------------
__global__ __launch_bounds__(256) void rmsnorm2_kernel(const float* __restrict__ ln2)
{
    int n = blockIdx.x;
    const float* row = g_h2 + (size_t)n * Dc;
    float vals[4];
    float local = 0.f;
#pragma unroll
    for (int i = 0; i < 4; i++) {
        float x = row[threadIdx.x + 256 * i];
        vals[i] = x;
        local += x * x;
    }
    __shared__ float red[256];
    red[threadIdx.x] = local;
    __syncthreads();
    for (int s = 128; s > 0; s >>= 1) {
        if (threadIdx.x < s) red[threadIdx.x] += red[threadIdx.x + s];
        __syncthreads();
    }
    float inv = rsqrtf(red[0] / (float)Dc + 1e-6f);
#pragma unroll
    for (int i = 0; i < 4; i++) {
        int d = threadIdx.x + 256 * i;
        g_mh[(size_t)n * Dc + d] = __float2half(vals[i] * inv * ln2[d]);
    }
}

// ---------------- fp16 tensor GEMM (ldmatrix A, 3-stage cp.async) ----------------
#define A_ST 20                        // A smem row stride (u32)
template<int NI>
__global__ __launch_bounds__(256) void tg16_kernel(
    const __half* __restrict__ A, int K,
    const uint32_t* __restrict__ B0, const uint32_t* __restrict__ B1,
    const uint32_t* __restrict__ B2,
    const float* __restrict__ bias0, const float* __restrict__ bias1,
    const float* __restrict__ bias2,
    const float* __restrict__ res,
    float* __restrict__ C0, float* __restrict__ C1, float* __restrict__ C2,
    int ldo, int blocksPerW,
    const int* __restrict__ bip, const int* __restrict__ tip,
    const float* __restrict__ gsp, float* __restrict__ outp)
{
    constexpr int BN  = NI * 32;
    constexpr int BSS = BN + 8;
    constexpr int ABUF = 3 * 128 * A_ST;

    int bm = blockIdx.x;
    int by = blockIdx.y;
    int w  = by / blocksPerW;
    int cb = by % blocksPerW;
    const uint32_t* B = (w == 0) ? B0 : (w == 1) ? B1 : B2;
    const float* bias = (w == 0) ? bias0 : (w == 1) ? bias1 : bias2;
    float*       C    = (w == 0) ? C0 : (w == 1) ? C1 : C2;

    extern __shared__ uint32_t ts[];
    uint32_t sbase = sptr(ts);

    int tid = threadIdx.x;
    int lane = tid & 31;
    int warp = tid >> 5;
    int warpM = warp & 1;
    int warpN = warp >> 1;
    int qr = lane >> 2;
    int qc = lane & 3;
    int lr  = (lane & 7) + (((lane >> 3) & 1) << 3);
    int lc4 = ((lane >> 4) & 1) * 4;

    float acc[4][NI][4];
#pragma unroll
    for (int mi = 0; mi < 4; mi++)
#pragma unroll
        for (int ni = 0; ni < NI; ni++)
#pragma unroll
            for (int j = 0; j < 4; j++) acc[mi][ni][j] = 0.f;

    const __half* Ablk = A + (size_t)bm * 128 * K;
    const uint32_t* Bblk = B + cb * BN;

    int nk = K >> 5;

    auto issue = [&](int kt, int buf) {
#pragma unroll
        for (int i = 0; i < 2; i++) {
            int idx = tid + 256 * i;
            int row = idx >> 2;
            int c4 = idx & 3;
            cp16(sbase + (buf * 128 * A_ST + row * A_ST + c4 * 4) * 4,
                 &Ablk[(size_t)row * K + kt * 32 + c4 * 8]);
        }
#pragma unroll
        for (int i = 0; i < BN / 64; i++) {
            int idx = tid + 256 * i;
            int row = idx / (BN / 4);
            int c = idx % (BN / 4);
            cp16(sbase + (ABUF + buf * 16 * BSS + row * BSS + c * 4) * 4,
                 &Bblk[(size_t)(kt * 16 + row) * ldo + c * 4]);
        }
        cp_commit();
    };

    issue(0, 0);
    issue(1, 1);

    for (int kt = 0; kt < nk; kt++) {
        if (kt + 1 < nk) cp_wait<1>(); else cp_wait<0>();
        __syncthreads();
        if (kt + 2 < nk) issue(kt + 2, (kt + 2) % 3);

        int buf = kt % 3;
        uint32_t abase = sbase + (buf * 128 * A_ST) * 4;
        const uint32_t* Bb = ts + ABUF + buf * 16 * BSS;
#pragma unroll
        for (int st = 0; st < 2; st++) {
            int j0 = st * 8 + qc;
            uint32_t a[4][4], b[NI][2];
#pragma unroll
            for (int mi = 0; mi < 4; mi++) {
                int row = warpM * 64 + mi * 16 + lr;
                ldsm_x4(a[mi], abase + (row * A_ST + st * 8 + lc4) * 4);
            }
#pragma unroll
            for (int ni = 0; ni < NI; ni++) {
                int nn = warpN * (NI * 8) + ni * 8 + qr;
                b[ni][0] = Bb[j0 * BSS + nn];
                b[ni][1] = Bb[(j0 + 4) * BSS + nn];
            }
#pragma unroll
            for (int mi = 0; mi < 4; mi++)
#pragma unroll
                for (int ni = 0; ni < NI; ni++)
                    mma_f16(acc[mi][ni], a[mi], b[ni]);
        }
    }

#pragma unroll
    for (int mi = 0; mi < 4; mi++) {
#pragma unroll
        for (int ni = 0; ni < NI; ni++) {
            int row = bm * 128 + warpM * 64 + mi * 16 + qr;
            int col = cb * BN + warpN * (NI * 8) + ni * 8 + 2 * qc;
            float2 lo, hi;
            lo.x = acc[mi][ni][0]; lo.y = acc[mi][ni][1];
            hi.x = acc[mi][ni][2]; hi.y = acc[mi][ni][3];
            if (bias) {
                float b0 = bias[col], b1 = bias[col + 1];
                lo.x += b0; lo.y += b1; hi.x += b0; hi.y += b1;
            }
            if (res) {
                const float* r0 = res + (size_t)row * ldo + col;
                const float* r1 = res + (size_t)(row + 8) * ldo + col;
                lo.x += r0[0]; lo.y += r0[1];
                hi.x += r1[0]; hi.y += r1[1];
            }
            if (outp) {
                int r1i = row + 8;
                float g0 = gsp[row], g1 = gsp[r1i];
                const float* s0 = g_sel + (size_t)row * Dc + col;
                const float* s1 = g_sel + (size_t)r1i * Dc + col;
                float2 o0, o1;
                o0.x = s0[0] + g0 * (lo.x - s0[0]);
                o0.y = s0[1] + g0 * (lo.y - s0[1]);
                o1.x = s1[0] + g1 * (hi.x - s1[0]);
                o1.y = s1[1] + g1 * (hi.y - s1[1]);
                size_t d0 = ((size_t)bip[row] * Sc + tip[row]) * Dc + col;
                size_t d1 = ((size_t)bip[r1i] * Sc + tip[r1i]) * Dc + col;
                *(float2*)&outp[d0] = o0;
                *(float2*)&outp[d1] = o1;
            } else {
                *(float2*)&C[(size_t)row * ldo + col] = lo;
                *(float2*)&C[(size_t)(row + 8) * ldo + col] = hi;
            }
        }
    }
}

#define TG16_SMEM_128 ((3*128*A_ST + 3*16*136) * 4)
#define TG16_SMEM_64  ((3*128*A_ST + 3*16*72) * 4)

// ---------------- dual gate/up GEMM + fused silu -> g_acth (half) ----------------
// Block computes gate AND up tiles at the same (m, col) from Wg/Wu, BN=64,
// epilogue: act = silu(gate) * up, written as half2. 1024 blocks.
__global__ __launch_bounds__(256) void tg16dual_kernel(
    const __half* __restrict__ A,
    const uint32_t* __restrict__ Bg, const uint32_t* __restrict__ Bu)
{
    constexpr int K = Dc;
    constexpr int BSS = 72;
    constexpr int ABUF = 3 * 128 * A_ST;
    constexpr int BGUF = ABUF + 3 * 16 * BSS;   // Bu buffers after Bg buffers

    int bm = blockIdx.x;
    int cb = blockIdx.y;

    extern __shared__ uint32_t ts[];
    uint32_t sbase = sptr(ts);

    int tid = threadIdx.x;
    int lane = tid & 31;
    int warp = tid >> 5;
    int warpM = warp & 1;
    int warpN = warp >> 1;
    int qr = lane >> 2;
    int qc = lane & 3;
    int lr  = (lane & 7) + (((lane >> 3) & 1) << 3);
    int lc4 = ((lane >> 4) & 1) * 4;

    float accg[4][2][4], accu[4][2][4];
#pragma unroll
    for (int mi = 0; mi < 4; mi++)
#pragma unroll
        for (int ni = 0; ni < 2; ni++)
#pragma unroll
            for (int j = 0; j < 4; j++) { accg[mi][ni][j] = 0.f; accu[mi][ni][j] = 0.f; }

    const __half* Ablk = A + (size_t)bm * 128 * K;
    const uint32_t* Bgblk = Bg + cb * 64;
    const uint32_t* Bublk = Bu + cb * 64;

    int nk = K >> 5;

    auto issue = [&](int kt, int buf) {
#pragma unroll
        for (int i = 0; i < 2; i++) {
            int idx = tid + 256 * i;
            int row = idx >> 2;
            int c4 = idx & 3;
            cp16(sbase + (buf * 128 * A_ST + row * A_ST + c4 * 4) * 4,
                 &Ablk[(size_t)row * K + kt * 32 + c4 * 8]);
        }
        {
            // each weight: 16 rows x 16 u32-chunks = 256 chunks
            int row = tid >> 4;
            int c = tid & 15;
            cp16(sbase + (ABUF + buf * 16 * BSS + row * BSS + c * 4) * 4,
                 &Bgblk[(size_t)(kt * 16 + row) * Fc + c * 4]);
            cp16(sbase + (BGUF + buf * 16 * BSS + row * BSS + c * 4) * 4,
                 &Bublk[(size_t)(kt * 16 + row) * Fc + c * 4]);
        }
        cp_commit();
    };

    issue(0, 0);
    issue(1, 1);

    for (int kt = 0; kt < nk; kt++) {
        if (kt + 1 < nk) cp_wait<1>(); else cp_wait<0>();
        __syncthreads();
        if (kt + 2 < nk) issue(kt + 2, (kt + 2) % 3);

        int buf = kt % 3;
        uint32_t abase = sbase + (buf * 128 * A_ST) * 4;
        const uint32_t* Bgb = ts + ABUF + buf * 16 * BSS;
        const uint32_t* Bub = ts + BGUF + buf * 16 * BSS;
#pragma unroll
        for (int st = 0; st < 2; st++) {
            int j0 = st * 8 + qc;
            uint32_t a[4][4], bg[2][2], bu[2][2];
#pragma unroll
            for (int mi = 0; mi < 4; mi++) {
                int row = warpM * 64 + mi * 16 + lr;
                ldsm_x4(a[mi], abase + (row * A_ST + st * 8 + lc4) * 4);
            }
#pragma unroll
            for (int ni = 0; ni < 2; ni++) {
                int nn = warpN * 16 + ni * 8 + qr;
                bg[ni][0] = Bgb[j0 * BSS + nn];
                bg[ni][1] = Bgb[(j0 + 4) * BSS + nn];
                bu[ni][0] = Bub[j0 * BSS + nn];
                bu[ni][1] = Bub[(j0 + 4) * BSS + nn];
            }
#pragma unroll
            for (int mi = 0; mi < 4; mi++)
#pragma unroll
                for (int ni = 0; ni < 2; ni++) {
                    mma_f16(accg[mi][ni], a[mi], bg[ni]);
                    mma_f16(accu[mi][ni], a[mi], bu[ni]);
                }
        }
    }

    // epilogue: act = silu(gate) * up -> half2
#pragma unroll
    for (int mi = 0; mi < 4; mi++) {
#pragma unroll
        for (int ni = 0; ni < 2; ni++) {
            int row = bm * 128 + warpM * 64 + mi * 16 + qr;
            int col = cb * 64 + warpN * 16 + ni * 8 + 2 * qc;
            float v0 = siluf(accg[mi][ni][0]) * accu[mi][ni][0];
            float v1 = siluf(accg[mi][ni][1]) * accu[mi][ni][1];
            float v2 = siluf(accg[mi][ni][2]) * accu[mi][ni][2];
            float v3 = siluf(accg[mi][ni][3]) * accu[mi][ni][3];
            *(uint32_t*)&g_acth[(size_t)row * Fc + col]       = packh2(v0, v1);
            *(uint32_t*)&g_acth[(size_t)(row + 8) * Fc + col] = packh2(v2, v3);
        }
    }
}

#define TGDUAL_SMEM ((3*128*A_ST + 6*16*72) * 4)

// ---------------- RoPE: g_q/g_k fp32 -> g_qh/g_kh half ----------------
__global__ __launch_bounds__(256) void rope_kernel()
{
    int idx = blockIdx.x * blockDim.x + threadIdx.x;
    int total = Nc * Hc * 32;
    const float* src = (idx < total) ? g_q : g_k;
    __half* dst = (idx < total) ? g_qh : g_kh;
    int r = idx % total;
    int n = r / (Hc * 32);
    int rem = r % (Hc * 32);
    int h = rem >> 5;
    int d = rem & 31;
    float c1 = g_cg[n * HDc + d],      s1 = g_sg[n * HDc + d];
    float c2 = g_cg[n * HDc + d + 32], s2 = g_sg[n * HDc + d + 32];
    const float* p = src + (size_t)n * Dc + h * HDc;
    float x1 = p[d], x2 = p[d + 32];
    __half* q = dst + (size_t)n * Dc + h * HDc;
    q[d]      = __float2half(x1 * c1 - x2 * s1);
    q[d + 32] = __float2half(x2 * c2 + x1 * s2);
}

// ---------------- pack V: g_v fp32 -> g_vph half2 [kp][1024] ----------------
__global__ __launch_bounds__(256) void vpack_kernel()
{
    int idx = blockIdx.x * 256 + threadIdx.x;
    int kp = idx >> 10;
    int c  = idx & 1023;
    g_vph[idx] = packh2(g_v[(size_t)(2 * kp) * Dc + c],
                        g_v[(size_t)(2 * kp + 1) * Dc + c]);
}

// ---------------- fused flash attention (fp16 m16n8k16, 3-stage cp.async) --------
#define FK2(buf) ((buf) * 2304)
#define FV2(buf) (6912 + (buf) * 2304)
#define FQ2 13824
#define FLASH_SMEM ((3*2304 + 3*2304 + 2304) * 4)

__global__ __launch_bounds__(128) void flash_kernel()
{
    int pair = blockIdx.x;
    int h = blockIdx.y;
    extern __shared__ uint32_t fsm[];
    uint32_t sbase = sptr(fsm);
    int tid = threadIdx.x;
    int warp = tid >> 5, lane = tid & 31;
    int qr = lane >> 2, qc = lane & 3;
    uint32_t* sQ = fsm + FQ2;
    uint32_t* sPw = sQ + warp * 16 * 36;

    auto issue_kv = [&](int kt, int buf) {
#pragma unroll
        for (int i = 0; i < 4; i++) {
            int idx = tid + 128 * i;
            int key = idx >> 3, c8 = idx & 7;
            cp16(sbase + (FK2(buf) + key * 36 + c8 * 4) * 4,
                 &g_kh[(size_t)(kt * 64 + key) * Dc + h * HDc + c8 * 8]);
        }
#pragma unroll
        for (int i = 0; i < 4; i++) {
            int idx = tid + 128 * i;
            int kpl = idx >> 4, c16 = idx & 15;
            cp16(sbase + (FV2(buf) + kpl * 72 + c16 * 4) * 4,
                 &g_vph[(size_t)(kt * 32 + kpl) * Dc + h * HDc + c16 * 4]);
        }
        cp_commit();
    };

#pragma unroll 1
    for (int pass = 0; pass < 2; pass++) {
        int qt = pass ? (31 - pair) : pair;

        __syncthreads();
#pragma unroll
        for (int i = 0; i < 4; i++) {
            int idx = tid + 128 * i;
            int row = idx >> 3, c8 = idx & 7;
            uint4 v = *(const uint4*)&g_qh[(size_t)(qt * 64 + row) * Dc + h * HDc + c8 * 8];
            *(uint4*)&sQ[row * 36 + c8 * 4] = v;
        }
        __syncthreads();

        uint32_t qa[4][4];
        int r0 = warp * 16 + qr;
#pragma unroll
        for (int kf = 0; kf < 4; kf++) {
            qa[kf][0] = sQ[r0 * 36 + 8 * kf + qc];
            qa[kf][1] = sQ[(r0 + 8) * 36 + 8 * kf + qc];
            qa[kf][2] = sQ[r0 * 36 + 8 * kf + 4 + qc];
            qa[kf][3] = sQ[(r0 + 8) * 36 + 8 * kf + 4 + qc];
        }
        __syncthreads();

        float m0 = -3e38f, m1 = -3e38f, l0 = 0.f, l1 = 0.f;
        float o[8][4];
#pragma unroll
        for (int ni = 0; ni < 8; ni++)
#pragma unroll
            for (int j = 0; j < 4; j++) o[ni][j] = 0.f;

        int ntiles = qt + 1;
        issue_kv(0, 0);
        if (ntiles > 1) issue_kv(1, 1);
        for (int kt = 0; kt < ntiles; kt++) {
            if (kt + 1 < ntiles) cp_wait<1>(); else cp_wait<0>();
            __syncthreads();
            if (kt + 2 < ntiles) issue_kv(kt + 2, (kt + 2) % 3);
            const uint32_t* sK = fsm + FK2(kt % 3);
            const uint32_t* sV = fsm + FV2(kt % 3);

            float s[8][4];
#pragma unroll
            for (int ni = 0; ni < 8; ni++)
#pragma unroll
                for (int j = 0; j < 4; j++) s[ni][j] = 0.f;
#pragma unroll
            for (int kf = 0; kf < 4; kf++) {
#pragma unroll
                for (int ni = 0; ni < 8; ni++) {
                    uint32_t b[2];
                    b[0] = sK[(8 * ni + qr) * 36 + 8 * kf + qc];
                    b[1] = sK[(8 * ni + qr) * 36 + 8 * kf + 4 + qc];
                    mma_f16(s[ni], qa[kf], b);
                }
            }

            bool diag = (kt == qt);
            int rl0 = warp * 16 + qr;
            int rl1 = rl0 + 8;
#pragma unroll
            for (int ni = 0; ni < 8; ni++) {
                int cl = 8 * ni + 2 * qc;
                s[ni][0] *= 0.125f; s[ni][1] *= 0.125f;
                s[ni][2] *= 0.125f; s[ni][3] *= 0.125f;
                if (diag) {
                    if (cl     > rl0) s[ni][0] = -1e30f;
                    if (cl + 1 > rl0) s[ni][1] = -1e30f;
                    if (cl     > rl1) s[ni][2] = -1e30f;
                    if (cl + 1 > rl1) s[ni][3] = -1e30f;
                }
            }

            float mx0 = -3e38f, mx1 = -3e38f;
#pragma unroll
            for (int ni = 0; ni < 8; ni++) {
                mx0 = fmaxf(mx0, fmaxf(s[ni][0], s[ni][1]));
                mx1 = fmaxf(mx1, fmaxf(s[ni][2], s[ni][3]));
            }
            mx0 = fmaxf(mx0, __shfl_xor_sync(0xffffffff, mx0, 1));
            mx0 = fmaxf(mx0, __shfl_xor_sync(0xffffffff, mx0, 2));
            mx1 = fmaxf(mx1, __shfl_xor_sync(0xffffffff, mx1, 1));
            mx1 = fmaxf(mx1, __shfl_xor_sync(0xffffffff, mx1, 2));
            float mn0 = fmaxf(m0, mx0), mn1 = fmaxf(m1, mx1);
            float sc0 = __expf(m0 - mn0), sc1 = __expf(m1 - mn1);
            m0 = mn0; m1 = mn1;
            float rs0 = 0.f, rs1 = 0.f;
#pragma unroll
            for (int ni = 0; ni < 8; ni++) {
                s[ni][0] = __expf(s[ni][0] - mn0);
                s[ni][1] = __expf(s[ni][1] - mn0);
                s[ni][2] = __expf(s[ni][2] - mn1);
                s[ni][3] = __expf(s[ni][3] - mn1);
                rs0 += s[ni][0] + s[ni][1];
                rs1 += s[ni][2] + s[ni][3];
            }
            rs0 += __shfl_xor_sync(0xffffffff, rs0, 1);
            rs0 += __shfl_xor_sync(0xffffffff, rs0, 2);
            rs1 += __shfl_xor_sync(0xffffffff, rs1, 1);
            rs1 += __shfl_xor_sync(0xffffffff, rs1, 2);
            l0 = l0 * sc0 + rs0;
            l1 = l1 * sc1 + rs1;
#pragma unroll
            for (int ni = 0; ni < 8; ni++) {
                o[ni][0] *= sc0; o[ni][1] *= sc0;
                o[ni][2] *= sc1; o[ni][3] *= sc1;
            }

#pragma unroll
            for (int ni = 0; ni < 8; ni++) {
                sPw[qr * 36 + 4 * ni + qc]       = packh2(s[ni][0], s[ni][1]);
                sPw[(qr + 8) * 36 + 4 * ni + qc] = packh2(s[ni][2], s[ni][3]);
            }
            __syncwarp();

#pragma unroll
            for (int kf = 0; kf < 4; kf++) {
                uint32_t a[4];
                a[0] = sPw[qr * 36 + 8 * kf + qc];
                a[1] = sPw[(qr + 8) * 36 + 8 * kf + qc];
                a[2] = sPw[qr * 36 + 8 * kf + 4 + qc];
                a[3] = sPw[(qr + 8) * 36 + 8 * kf + 4 + qc];
#pragma unroll
                for (int ni = 0; ni < 8; ni++) {
                    uint32_t b[2];
                    b[0] = sV[(8 * kf + qc) * 72 + 8 * ni + qr];
                    b[1] = sV[(8 * kf + 4 + qc) * 72 + 8 * ni + qr];
                    mma_f16(o[ni], a, b);
                }
            }
            __syncwarp();
        }

        float li0 = 1.f / l0, li1 = 1.f / l1;
        int rg0 = qt * 64 + warp * 16 + qr;
#pragma unroll
        for (int ni = 0; ni < 8; ni++) {
            int col = h * HDc + 8 * ni + 2 * qc;
            *(uint32_t*)&g_ctxh[(size_t)rg0 * Dc + col] =
                packh2(o[ni][0] * li0, o[ni][1] * li0);
            *(uint32_t*)&g_ctxh[(size_t)(rg0 + 8) * Dc + col] =
                packh2(o[ni][2] * li1, o[ni][3] * li1);
        }
    }
}

// ---------------- driver ----------------
extern "C" void kernel_launch(void* const* d_in, const int* in_sizes, int n_in,
                              void* d_out, int out_size)
{
    const float* hidden = (const float*)d_in[0];
    const int*   bi     = (const int*)d_in[1];
    const int*   ti     = (const int*)d_in[2];
    const float* gs     = (const float*)d_in[3];
    const float* cosp   = (const float*)d_in[4];
    const float* sinp   = (const float*)d_in[5];
    const float* Wq     = (const float*)d_in[6];
    const float* bq     = (const float*)d_in[7];
    const float* Wk     = (const float*)d_in[8];
    const float* bk     = (const float*)d_in[9];
    const float* Wv     = (const float*)d_in[10];
    const float* bv     = (const float*)d_in[11];
    const float* Wo     = (const float*)d_in[12];
    const float* Wg     = (const float*)d_in[13];
    const float* Wu     = (const float*)d_in[14];
    const float* Wd     = (const float*)d_in[15];
    const float* ln1    = (const float*)d_in[16];
    const float* ln2    = (const float*)d_in[17];
    float* out = (float*)d_out;

    static float *p_sel = nullptr, *p_q = nullptr, *p_k = nullptr, *p_v = nullptr,
                 *p_h2 = nullptr;
    static __half *p_hh = nullptr, *p_mh = nullptr, *p_ctxh = nullptr, *p_acth = nullptr;
    static uint32_t *p_wh = nullptr;
    static bool inited = false;
    if (!inited) {
        cudaGetSymbolAddress((void**)&p_sel, g_sel);
        cudaGetSymbolAddress((void**)&p_q, g_q);
        cudaGetSymbolAddress((void**)&p_k, g_k);
        cudaGetSymbolAddress((void**)&p_v, g_v);
        cudaGetSymbolAddress((void**)&p_h2, g_h2);
        cudaGetSymbolAddress((void**)&p_hh, g_hh);
        cudaGetSymbolAddress((void**)&p_mh, g_mh);
        cudaGetSymbolAddress((void**)&p_ctxh, g_ctxh);
        cudaGetSymbolAddress((void**)&p_acth, g_acth);
        cudaGetSymbolAddress((void**)&p_wh, g_wh);
        cudaFuncSetAttribute(flash_kernel,
                             cudaFuncAttributeMaxDynamicSharedMemorySize, FLASH_SMEM);
        cudaFuncSetAttribute(tg16_kernel<4>,
                             cudaFuncAttributeMaxDynamicSharedMemorySize, TG16_SMEM_128);
        cudaFuncSetAttribute(tg16_kernel<2>,
                             cudaFuncAttributeMaxDynamicSharedMemorySize, TG16_SMEM_64);
        cudaFuncSetAttribute(tg16dual_kernel,
                             cudaFuncAttributeMaxDynamicSharedMemorySize, TGDUAL_SMEM);
        inited = true;
    }
    uint32_t* WqP = p_wh;
    uint32_t* WkP = p_wh + 524288;
    uint32_t* WvP = p_wh + 1048576;
    uint32_t* WoP = p_wh + 1572864;
    uint32_t* WgP = p_wh + 2097152;
    uint32_t* WuP = p_wh + 4194304;
    uint32_t* WdP = p_wh + 6291456;

    // 1) copy hidden -> out
    copy_kernel<<<(Bc * Sc * Dc / 4) / 256, 256>>>((const float4*)hidden, (float4*)out);

    // 2) convert weights to packed half2
    wconv_kernel<<<dim3(8192, 7), 256>>>(Wq, Wk, Wv, Wo, Wg, Wu, Wd);

    // 3) gather + rmsnorm(ln1) -> g_hh
    gather_norm_kernel<<<Nc, 256>>>(hidden, bi, ti, cosp, sinp, ln1);

    // 4) QKV fused fp16 GEMM  (BN=128, 384 blocks)
    tg16_kernel<4><<<dim3(16, 24), 256, TG16_SMEM_128>>>(
        p_hh, Dc, WqP, WkP, WvP, bq, bk, bv, nullptr, p_q, p_k, p_v, Dc, 8,
        nullptr, nullptr, nullptr, nullptr);

    // 5) RoPE -> g_qh/g_kh (half); pack V -> g_vph
    rope_kernel<<<(2 * Nc * Hc * 32) / 256, 256>>>();
    vpack_kernel<<<(Nc / 2 * Dc) / 256, 256>>>();

    // 6) fused fp16 flash attention -> g_ctxh
    flash_kernel<<<dim3(16, Hc), 128, FLASH_SMEM>>>();

    // 7) h2 = sel + ctx @ Wo  (BN=64, 256 blocks)
    tg16_kernel<2><<<dim3(16, 16), 256, TG16_SMEM_64>>>(
        p_ctxh, Dc, WoP, WoP, WoP, nullptr, nullptr, nullptr, p_sel,
        p_h2, p_h2, p_h2, Dc, 16,
        nullptr, nullptr, nullptr, nullptr);

    // 8) m = rmsnorm(h2, ln2) -> g_mh
    rmsnorm2_kernel<<<Nc, 256>>>(ln2);

    // 9) dual gate/up GEMM + fused silu -> g_acth  (1024 blocks)
    tg16dual_kernel<<<dim3(16, 64), 256, TGDUAL_SMEM>>>(p_mh, WgP, WuP);

    // 10) down-proj + residual + fused gated scatter into out (BN=64, 256 blocks)
    tg16_kernel<2><<<dim3(16, 16), 256, TG16_SMEM_64>>>(
        p_acth, Fc, WdP, WdP, WdP, nullptr, nullptr, nullptr, p_h2,
        nullptr, nullptr, nullptr, Dc, 16,
        bi, ti, gs, out);
}